// round 2
// baseline (speedup 1.0000x reference)
#include <cuda_runtime.h>
#include <math.h>

#define BB 2
#define LL 2048
#define DD 768
#define HH 12
#define RR 128
#define DH 64
#define NROWS (BB*LL)        // 4096
#define NC 32                // chunks per sequence
#define CT 64                // chunk length (NC*CT == LL)
#define BHN (BB*HH)          // 24
#define PI_F 3.14159265358979323846f

// ---------------- scratch (device globals; no allocation allowed) ----------
__device__ float g_xn[NROWS*DD];            // layernorm(x)
__device__ float g_qkv[NROWS*3*DD];         // qkv
__device__ float g_hsem[NROWS*RR];          // silu(x @ W_sem_down)
__device__ float g_hctx[NROWS*RR];
__device__ float g_sem[NROWS*2*DD];         // hsem @ W_sem_up
__device__ float g_ctx[NROWS*2*DD];
__device__ float g_qf[NROWS*DD];            // (b,h,l,dh) layout
__device__ float g_kf[NROWS*DD];
__device__ float g_vf[NROWS*DD];
__device__ float g_S[BHN*NC*DH*DH];         // chunk k (x) v sums -> exclusive prefix
__device__ float g_z[BHN*NC*DH];            // chunk k sums -> exclusive prefix
__device__ float g_attn[NROWS*DD];          // attention output, (row, D) layout

// ---------------- layernorm ------------------------------------------------
__global__ void ln_kernel(const float* __restrict__ x,
                          const float* __restrict__ gamma,
                          const float* __restrict__ beta) {
    int row = blockIdx.x;
    const float* xr = x + row*DD;
    int t = threadIdx.x;                     // 256 threads, 3 elems each
    float v0 = xr[t], v1 = xr[t+256], v2 = xr[t+512];
    __shared__ float red[256], red2[256];
    red[t]  = v0+v1+v2;
    red2[t] = v0*v0+v1*v1+v2*v2;
    __syncthreads();
    for (int o = 128; o > 0; o >>= 1) {
        if (t < o) { red[t] += red[t+o]; red2[t] += red2[t+o]; }
        __syncthreads();
    }
    float mu  = red[0] * (1.0f/DD);
    float var = red2[0] * (1.0f/DD) - mu*mu;
    float inv = rsqrtf(var + 1e-5f);
    float* o = g_xn + row*DD;
    o[t]     = (v0-mu)*inv*gamma[t]     + beta[t];
    o[t+256] = (v1-mu)*inv*gamma[t+256] + beta[t+256];
    o[t+512] = (v2-mu)*inv*gamma[t+512] + beta[t+512];
}

// ---------------- generic tiled fp32 GEMM ---------------------------------
// C[M,N] = A[M,K] @ B[K,N] (+bias) (+silu).  EPI: 0=none, 1=bias, 2=silu
// All dims are multiples of tile sizes for this problem -> no bounds checks.
#define GBM 64
#define GBN 64
#define GBK 16
template<int EPI>
__global__ void gemm_kernel(const float* __restrict__ A, const float* __restrict__ B,
                            const float* __restrict__ bias, float* __restrict__ C,
                            int M, int N, int K) {
    __shared__ float As[GBK][GBM];
    __shared__ float Bs[GBK][GBN];
    int tx = threadIdx.x, ty = threadIdx.y;      // 16x16
    int tid = ty*16 + tx;
    int row0 = blockIdx.y*GBM, col0 = blockIdx.x*GBN;
    float acc[4][4] = {};
    for (int k0 = 0; k0 < K; k0 += GBK) {
        #pragma unroll
        for (int i = 0; i < 4; i++) {
            int idx = tid + i*256;               // 0..1023
            int m = idx / GBK, kk = idx % GBK;
            As[kk][m] = A[(row0+m)*K + k0 + kk];
        }
        #pragma unroll
        for (int i = 0; i < 4; i++) {
            int idx = tid + i*256;
            int kk = idx / GBN, n = idx % GBN;
            Bs[kk][n] = B[(k0+kk)*N + col0 + n];
        }
        __syncthreads();
        #pragma unroll
        for (int kk = 0; kk < GBK; kk++) {
            float a[4], b[4];
            #pragma unroll
            for (int i = 0; i < 4; i++) a[i] = As[kk][ty*4+i];
            #pragma unroll
            for (int j = 0; j < 4; j++) b[j] = Bs[kk][tx*4+j];
            #pragma unroll
            for (int i = 0; i < 4; i++)
                #pragma unroll
                for (int j = 0; j < 4; j++)
                    acc[i][j] += a[i]*b[j];
        }
        __syncthreads();
    }
    #pragma unroll
    for (int i = 0; i < 4; i++) {
        int m = row0 + ty*4 + i;
        #pragma unroll
        for (int j = 0; j < 4; j++) {
            int n = col0 + tx*4 + j;
            float v = acc[i][j];
            if (EPI == 1) v += bias[n];
            if (EPI == 2) v = v / (1.0f + expf(-v));   // silu
            C[m*N + n] = v;
        }
    }
}

// ---------------- gate + feature map + head reshape -----------------------
__device__ __forceinline__ float softplus_f(float a) {
    return a > 20.0f ? a : log1pf(expf(a));
}
__global__ void gate_kernel(const float* __restrict__ temperature,
                            float* __restrict__ gate_out) {
    int idx = blockIdx.x*256 + threadIdx.x;       // < NROWS*DD
    int row = idx / DD, d = idx - row*DD;
    const float* sr = g_sem + row*(2*DD);
    const float* cr = g_ctx + row*(2*DD);
    float sa = softplus_f(sr[d]);
    float sp = tanhf(sr[DD + d]) * PI_F;
    float ca = softplus_f(cr[d]);
    float cp = tanhf(cr[DD + d]) * PI_F;
    float inter = sa * ca * cosf(sp - cp) * temperature[0];
    float gate = 1.0f / (1.0f + expf(-inter));
    gate_out[idx] = gate;

    const float* qr = g_qkv + row*(3*DD);
    float q = qr[d];
    float k = qr[DD + d] * (1.0f + gate);
    float v = qr[2*DD + d];
    float qfv = q > 0.0f ? q + 1.0f : expf(q);    // elu(q)+1
    float kfv = k > 0.0f ? k + 1.0f : expf(k);
    int b = row / LL, l = row - b*LL;
    int h = d / DH, dh = d - h*DH;
    int hid = ((b*HH + h)*LL + l)*DH + dh;
    g_qf[hid] = qfv;
    g_kf[hid] = kfv;
    g_vf[hid] = v;
}

// ---------------- phase 1: per-chunk k(x)v and k sums ---------------------
__global__ void chunksum_kernel() {
    int c  = blockIdx.x;      // chunk
    int bh = blockIdx.y;      // (b,h)
    __shared__ float ks[CT][DH];
    __shared__ float vs[CT][DH];
    int tid = threadIdx.x;    // 256
    int base = (bh*LL + c*CT)*DH;
    for (int i = tid; i < CT*DH; i += 256) {
        ks[i/DH][i%DH] = g_kf[base + i];
        vs[i/DH][i%DH] = g_vf[base + i];
    }
    __syncthreads();
    int d  = tid >> 2;                 // 0..63
    int e0 = (tid & 3) * 16;
    float acc[16] = {};
    float zacc = 0.0f;
    for (int l = 0; l < CT; l++) {
        float kd = ks[l][d];
        zacc += kd;
        #pragma unroll
        for (int u = 0; u < 16; u++) acc[u] += kd * vs[l][e0 + u];
    }
    float* Sp = g_S + (size_t)(bh*NC + c)*DH*DH;
    #pragma unroll
    for (int u = 0; u < 16; u++) Sp[d*DH + e0 + u] = acc[u];
    if ((tid & 3) == 0) g_z[(bh*NC + c)*DH + d] = zacc * 0.25f * 4.0f;  // == zacc
}

// ---------------- phase 2: exclusive scan over chunks (in place) ----------
__global__ void scan_kernel() {
    int bh = blockIdx.x;
    int tid = threadIdx.x;    // 256
    for (int e = tid; e < DH*DH; e += 256) {
        float run = 0.0f;
        for (int c = 0; c < NC; c++) {
            float* p = g_S + (size_t)(bh*NC + c)*DH*DH + e;
            float t = *p; *p = run; run += t;
        }
    }
    if (tid < DH) {
        float run = 0.0f;
        for (int c = 0; c < NC; c++) {
            float* p = g_z + (bh*NC + c)*DH + tid;
            float t = *p; *p = run; run += t;
        }
    }
}

// ---------------- phase 3: intra-chunk causal + inter-chunk state ---------
__global__ void attn_kernel() {
    int c  = blockIdx.x;
    int bh = blockIdx.y;
    __shared__ float qs[CT][DH+1];
    __shared__ float ks[CT][DH+1];
    int tid = threadIdx.x;    // 256
    int base = (bh*LL + c*CT)*DH;
    for (int i = tid; i < CT*DH; i += 256) {
        qs[i/DH][i%DH] = g_qf[base + i];
        ks[i/DH][i%DH] = g_kf[base + i];
    }
    __syncthreads();
    int i  = tid >> 2;                 // row in chunk
    int e0 = (tid & 3) * 16;           // output slice
    const float* Sp = g_S + (size_t)(bh*NC + c)*DH*DH;
    const float* zp = g_z + (bh*NC + c)*DH;
    const float* vg = g_vf + base;

    float acc[16] = {};
    float den = 1e-6f;
    // inter-chunk: q[i] @ S_prev, q[i] . z_prev
    for (int d = 0; d < DH; d++) {
        float qd = qs[i][d];
        den += qd * zp[d];
        const float* sr = Sp + d*DH + e0;
        #pragma unroll
        for (int u = 0; u < 16; u++) acc[u] += qd * sr[u];
    }
    // intra-chunk causal
    for (int j = 0; j <= i; j++) {
        float s = 0.0f;
        #pragma unroll
        for (int d = 0; d < DH; d++) s += qs[i][d] * ks[j][d];
        den += s;
        const float* vr = vg + j*DH + e0;
        #pragma unroll
        for (int u = 0; u < 16; u++) acc[u] += s * vr[u];
    }
    int b = bh / HH, h = bh - b*HH;
    int l = c*CT + i;
    float* orow = g_attn + (size_t)(b*LL + l)*DD + h*DH + e0;
    float invd = 1.0f / den;
    #pragma unroll
    for (int u = 0; u < 16; u++) orow[u] = acc[u] * invd;
}

// ---------------- launch ---------------------------------------------------
extern "C" void kernel_launch(void* const* d_in, const int* in_sizes, int n_in,
                              void* d_out, int out_size) {
    const float* x          = (const float*)d_in[0];
    const float* W_qkv      = (const float*)d_in[1];
    const float* b_qkv      = (const float*)d_in[2];
    const float* W_sem_down = (const float*)d_in[3];
    const float* W_sem_up   = (const float*)d_in[4];
    const float* W_ctx_down = (const float*)d_in[5];
    const float* W_ctx_up   = (const float*)d_in[6];
    const float* temperature= (const float*)d_in[7];
    const float* W_proj     = (const float*)d_in[8];
    const float* b_proj     = (const float*)d_in[9];
    const float* gamma      = (const float*)d_in[10];
    const float* beta       = (const float*)d_in[11];
    float* y_out    = (float*)d_out;
    float* gate_out = y_out + (size_t)NROWS*DD;

    float *p_xn, *p_qkv, *p_hsem, *p_hctx, *p_sem, *p_ctx, *p_attn;
    cudaGetSymbolAddress((void**)&p_xn,   g_xn);
    cudaGetSymbolAddress((void**)&p_qkv,  g_qkv);
    cudaGetSymbolAddress((void**)&p_hsem, g_hsem);
    cudaGetSymbolAddress((void**)&p_hctx, g_hctx);
    cudaGetSymbolAddress((void**)&p_sem,  g_sem);
    cudaGetSymbolAddress((void**)&p_ctx,  g_ctx);
    cudaGetSymbolAddress((void**)&p_attn, g_attn);

    dim3 tb(16, 16);

    ln_kernel<<<NROWS, 256>>>(x, gamma, beta);

    // qkv = xn @ W_qkv + b_qkv
    gemm_kernel<1><<<dim3(3*DD/GBN, NROWS/GBM), tb>>>(p_xn, W_qkv, b_qkv, p_qkv, NROWS, 3*DD, DD);
    // low-rank branches (note: use raw x, not xn)
    gemm_kernel<2><<<dim3(RR/GBN,   NROWS/GBM), tb>>>(x, W_sem_down, nullptr, p_hsem, NROWS, RR, DD);
    gemm_kernel<2><<<dim3(RR/GBN,   NROWS/GBM), tb>>>(x, W_ctx_down, nullptr, p_hctx, NROWS, RR, DD);
    gemm_kernel<0><<<dim3(2*DD/GBN, NROWS/GBM), tb>>>(p_hsem, W_sem_up, nullptr, p_sem, NROWS, 2*DD, RR);
    gemm_kernel<0><<<dim3(2*DD/GBN, NROWS/GBM), tb>>>(p_hctx, W_ctx_up, nullptr, p_ctx, NROWS, 2*DD, RR);

    // gate + feature maps + head layout (writes gate to output)
    gate_kernel<<<(NROWS*DD)/256, 256>>>(temperature, gate_out);

    // chunked causal linear attention
    chunksum_kernel<<<dim3(NC, BHN), 256>>>();
    scan_kernel<<<BHN, 256>>>();
    attn_kernel<<<dim3(NC, BHN), 256>>>();

    // y = attn @ W_proj + b_proj
    gemm_kernel<1><<<dim3(DD/GBN, NROWS/GBM), tb>>>(p_attn, W_proj, b_proj, y_out, NROWS, DD, DD);
}

// round 4
// speedup vs baseline: 2.3913x; 2.3913x over previous
#include <cuda_runtime.h>
#include <math.h>
#include <stdint.h>

#define BB 2
#define LL 2048
#define DD 768
#define HH 12
#define RR 128
#define DH 64
#define NROWS (BB*LL)        // 4096
#define NC 32
#define CT 64
#define BHN (BB*HH)
#define PI_F 3.14159265358979323846f

// ---------------- scratch ---------------------------------------------------
__device__ float g_xn[NROWS*DD];
__device__ float g_qkv[NROWS*3*DD];
__device__ float g_hsem[NROWS*RR];
__device__ float g_hctx[NROWS*RR];
__device__ float g_sem[NROWS*2*DD];
__device__ float g_ctx[NROWS*2*DD];
__device__ float g_qf[NROWS*DD];
__device__ float g_kf[NROWS*DD];
__device__ float g_vf[NROWS*DD];
__device__ float g_S[BHN*NC*DH*DH];
__device__ float g_z[BHN*NC*DH];
__device__ float g_attn[NROWS*DD];

// ---------------- TF32 mma.sync GEMM ----------------------------------------
// C[M,N] = A[M,K] @ B[K,N] (+bias)(+silu), hi/lo 3xTF32 split for fp32 accuracy.
// CTA tile 128x128, BK=32, 256 threads = 8 warps (warp tile 32x64).
// EPI: 0=none, 1=bias, 2=silu

__device__ __forceinline__ void mma_tf32(float* c, const uint32_t* a,
                                         uint32_t b0, uint32_t b1) {
    asm volatile(
        "mma.sync.aligned.m16n8k8.row.col.f32.tf32.tf32.f32 "
        "{%0,%1,%2,%3}, {%4,%5,%6,%7}, {%8,%9}, {%0,%1,%2,%3};"
        : "+f"(c[0]), "+f"(c[1]), "+f"(c[2]), "+f"(c[3])
        : "r"(a[0]), "r"(a[1]), "r"(a[2]), "r"(a[3]), "r"(b0), "r"(b1));
}
__device__ __forceinline__ float4 hi4(float4 v) {
    float4 h;
    h.x = __uint_as_float(__float_as_uint(v.x) & 0xFFFFE000u);
    h.y = __uint_as_float(__float_as_uint(v.y) & 0xFFFFE000u);
    h.z = __uint_as_float(__float_as_uint(v.z) & 0xFFFFE000u);
    h.w = __uint_as_float(__float_as_uint(v.w) & 0xFFFFE000u);
    return h;
}

#define APAD 36
#define BPAD 132
// floats: Ah[128*36], Al[128*36], Bh[32*132], Bl[32*132]
#define SM_AH 0
#define SM_AL (128*APAD)
#define SM_BH (2*128*APAD)
#define SM_BL (2*128*APAD + 32*BPAD)
#define TGE_SMEM ((2*128*APAD + 2*32*BPAD) * 4)

template<int EPI>
__global__ void __launch_bounds__(256, 1) tgemm_kernel(
    const float* __restrict__ A, const float* __restrict__ B,
    const float* __restrict__ bias, float* __restrict__ C,
    int N, int K) {
    extern __shared__ float sm[];
    int tid = threadIdx.x;
    int lane = tid & 31, wid = tid >> 5;
    int wm = wid & 3, wn = wid >> 2;          // warp tile: rows wm*32, cols wn*64
    int g = lane >> 2, t4 = lane & 3;
    int m0 = blockIdx.y * 128, n0 = blockIdx.x * 128;

    // global load indexing (per thread: 4 float4 of A, 4 float4 of B)
    int arow[4], acol4[4], brow[4], bcol4[4];
    #pragma unroll
    for (int i = 0; i < 4; i++) {
        int idx = tid + i * 256;              // 0..1023
        arow[i] = idx >> 3;  acol4[i] = idx & 7;     // A: 128 rows x 8 float4
        brow[i] = idx >> 5;  bcol4[i] = idx & 31;    // B: 32 rows x 32 float4
    }

    float4 ra[4], rb[4];
    #pragma unroll
    for (int i = 0; i < 4; i++) {
        ra[i] = *(const float4*)(A + (size_t)(m0 + arow[i]) * K + acol4[i] * 4);
        rb[i] = *(const float4*)(B + (size_t)brow[i] * N + n0 + bcol4[i] * 4);
    }

    float c[2][8][4];
    #pragma unroll
    for (int mt = 0; mt < 2; mt++)
        #pragma unroll
        for (int nt = 0; nt < 8; nt++)
            #pragma unroll
            for (int r = 0; r < 4; r++) c[mt][nt][r] = 0.0f;

    int nstages = K >> 5;
    for (int s = 0; s < nstages; s++) {
        // store current regs -> smem (hi/lo split)
        #pragma unroll
        for (int i = 0; i < 4; i++) {
            float4 h = hi4(ra[i]);
            float4 l = make_float4(ra[i].x - h.x, ra[i].y - h.y, ra[i].z - h.z, ra[i].w - h.w);
            *(float4*)(sm + SM_AH + arow[i] * APAD + acol4[i] * 4) = h;
            *(float4*)(sm + SM_AL + arow[i] * APAD + acol4[i] * 4) = l;
            float4 hb = hi4(rb[i]);
            float4 lb = make_float4(rb[i].x - hb.x, rb[i].y - hb.y, rb[i].z - hb.z, rb[i].w - hb.w);
            *(float4*)(sm + SM_BH + brow[i] * BPAD + bcol4[i] * 4) = hb;
            *(float4*)(sm + SM_BL + brow[i] * BPAD + bcol4[i] * 4) = lb;
        }
        __syncthreads();

        // prefetch next chunk while computing this one
        if (s + 1 < nstages) {
            int k0 = (s + 1) << 5;
            #pragma unroll
            for (int i = 0; i < 4; i++) {
                ra[i] = *(const float4*)(A + (size_t)(m0 + arow[i]) * K + k0 + acol4[i] * 4);
                rb[i] = *(const float4*)(B + (size_t)(k0 + brow[i]) * N + n0 + bcol4[i] * 4);
            }
        }

        #pragma unroll
        for (int ks = 0; ks < 4; ks++) {
            uint32_t ah[2][4], al[2][4];
            #pragma unroll
            for (int mt = 0; mt < 2; mt++) {
                int r0 = wm * 32 + mt * 16;
                const float* ph = sm + SM_AH;
                const float* pl = sm + SM_AL;
                int kb = ks * 8;
                ah[mt][0] = __float_as_uint(ph[(r0 + g    ) * APAD + kb + t4    ]);
                ah[mt][1] = __float_as_uint(ph[(r0 + g + 8) * APAD + kb + t4    ]);
                ah[mt][2] = __float_as_uint(ph[(r0 + g    ) * APAD + kb + t4 + 4]);
                ah[mt][3] = __float_as_uint(ph[(r0 + g + 8) * APAD + kb + t4 + 4]);
                al[mt][0] = __float_as_uint(pl[(r0 + g    ) * APAD + kb + t4    ]);
                al[mt][1] = __float_as_uint(pl[(r0 + g + 8) * APAD + kb + t4    ]);
                al[mt][2] = __float_as_uint(pl[(r0 + g    ) * APAD + kb + t4 + 4]);
                al[mt][3] = __float_as_uint(pl[(r0 + g + 8) * APAD + kb + t4 + 4]);
            }
            #pragma unroll
            for (int nt = 0; nt < 8; nt++) {
                int nb = wn * 64 + nt * 8 + g;
                int kb = ks * 8;
                uint32_t bh0 = __float_as_uint(sm[SM_BH + (kb + t4    ) * BPAD + nb]);
                uint32_t bh1 = __float_as_uint(sm[SM_BH + (kb + t4 + 4) * BPAD + nb]);
                uint32_t bl0 = __float_as_uint(sm[SM_BL + (kb + t4    ) * BPAD + nb]);
                uint32_t bl1 = __float_as_uint(sm[SM_BL + (kb + t4 + 4) * BPAD + nb]);
                #pragma unroll
                for (int mt = 0; mt < 2; mt++) {
                    mma_tf32(c[mt][nt], ah[mt], bh0, bh1);   // Ah*Bh
                    mma_tf32(c[mt][nt], ah[mt], bl0, bl1);   // Ah*Bl
                    mma_tf32(c[mt][nt], al[mt], bh0, bh1);   // Al*Bh
                }
            }
        }
        __syncthreads();
    }

    // ---- epilogue: direct global writes (float2 per fragment row) ----
    #pragma unroll
    for (int mt = 0; mt < 2; mt++) {
        int row = m0 + wm * 32 + mt * 16 + g;
        #pragma unroll
        for (int nt = 0; nt < 8; nt++) {
            int col = n0 + wn * 64 + nt * 8 + 2 * t4;
            float v0 = c[mt][nt][0], v1 = c[mt][nt][1];
            float v2 = c[mt][nt][2], v3 = c[mt][nt][3];
            if (EPI == 1) {
                float b0 = bias[col], b1 = bias[col + 1];
                v0 += b0; v1 += b1; v2 += b0; v3 += b1;
            }
            if (EPI == 2) {
                v0 = v0 / (1.0f + expf(-v0));
                v1 = v1 / (1.0f + expf(-v1));
                v2 = v2 / (1.0f + expf(-v2));
                v3 = v3 / (1.0f + expf(-v3));
            }
            *(float2*)(C + (size_t)row * N + col)       = make_float2(v0, v1);
            *(float2*)(C + (size_t)(row + 8) * N + col) = make_float2(v2, v3);
        }
    }
}

// ---------------- layernorm -------------------------------------------------
__global__ void ln_kernel(const float* __restrict__ x,
                          const float* __restrict__ gamma,
                          const float* __restrict__ beta) {
    int row = blockIdx.x;
    const float* xr = x + row*DD;
    int t = threadIdx.x;
    float v0 = xr[t], v1 = xr[t+256], v2 = xr[t+512];
    __shared__ float red[256], red2[256];
    red[t]  = v0+v1+v2;
    red2[t] = v0*v0+v1*v1+v2*v2;
    __syncthreads();
    for (int o = 128; o > 0; o >>= 1) {
        if (t < o) { red[t] += red[t+o]; red2[t] += red2[t+o]; }
        __syncthreads();
    }
    float mu  = red[0] * (1.0f/DD);
    float var = red2[0] * (1.0f/DD) - mu*mu;
    float inv = rsqrtf(var + 1e-5f);
    float* o = g_xn + row*DD;
    o[t]     = (v0-mu)*inv*gamma[t]     + beta[t];
    o[t+256] = (v1-mu)*inv*gamma[t+256] + beta[t+256];
    o[t+512] = (v2-mu)*inv*gamma[t+512] + beta[t+512];
}

// ---------------- gate + feature map + head reshape -------------------------
__device__ __forceinline__ float softplus_f(float a) {
    return a > 20.0f ? a : log1pf(expf(a));
}
__global__ void gate_kernel(const float* __restrict__ temperature,
                            float* __restrict__ gate_out) {
    int idx = blockIdx.x*256 + threadIdx.x;
    int row = idx / DD, d = idx - row*DD;
    const float* sr = g_sem + row*(2*DD);
    const float* cr = g_ctx + row*(2*DD);
    float sa = softplus_f(sr[d]);
    float sp = tanhf(sr[DD + d]) * PI_F;
    float ca = softplus_f(cr[d]);
    float cp = tanhf(cr[DD + d]) * PI_F;
    float inter = sa * ca * cosf(sp - cp) * temperature[0];
    float gate = 1.0f / (1.0f + expf(-inter));
    gate_out[idx] = gate;

    const float* qr = g_qkv + row*(3*DD);
    float q = qr[d];
    float k = qr[DD + d] * (1.0f + gate);
    float v = qr[2*DD + d];
    float qfv = q > 0.0f ? q + 1.0f : expf(q);
    float kfv = k > 0.0f ? k + 1.0f : expf(k);
    int b = row / LL, l = row - b*LL;
    int h = d / DH, dh = d - h*DH;
    int hid = ((b*HH + h)*LL + l)*DH + dh;
    g_qf[hid] = qfv;
    g_kf[hid] = kfv;
    g_vf[hid] = v;
}

// ---------------- chunked linear attention ----------------------------------
__global__ void chunksum_kernel() {
    int c  = blockIdx.x;
    int bh = blockIdx.y;
    __shared__ float ks[CT][DH];
    __shared__ float vs[CT][DH];
    int tid = threadIdx.x;
    int base = (bh*LL + c*CT)*DH;
    for (int i = tid; i < CT*DH; i += 256) {
        ks[i/DH][i%DH] = g_kf[base + i];
        vs[i/DH][i%DH] = g_vf[base + i];
    }
    __syncthreads();
    int d  = tid >> 2;
    int e0 = (tid & 3) * 16;
    float acc[16] = {};
    float zacc = 0.0f;
    for (int l = 0; l < CT; l++) {
        float kd = ks[l][d];
        zacc += kd;
        #pragma unroll
        for (int u = 0; u < 16; u++) acc[u] += kd * vs[l][e0 + u];
    }
    float* Sp = g_S + (size_t)(bh*NC + c)*DH*DH;
    #pragma unroll
    for (int u = 0; u < 16; u++) Sp[d*DH + e0 + u] = acc[u];
    if ((tid & 3) == 0) g_z[(bh*NC + c)*DH + d] = zacc;
}

__global__ void scan_kernel() {
    int bh = blockIdx.x;
    int tid = threadIdx.x;
    for (int e = tid; e < DH*DH; e += 256) {
        float run = 0.0f;
        for (int c = 0; c < NC; c++) {
            float* p = g_S + (size_t)(bh*NC + c)*DH*DH + e;
            float t = *p; *p = run; run += t;
        }
    }
    if (tid < DH) {
        float run = 0.0f;
        for (int c = 0; c < NC; c++) {
            float* p = g_z + (bh*NC + c)*DH + tid;
            float t = *p; *p = run; run += t;
        }
    }
}

__global__ void attn_kernel() {
    int c  = blockIdx.x;
    int bh = blockIdx.y;
    __shared__ float qs[CT][DH+1];
    __shared__ float ks[CT][DH+1];
    int tid = threadIdx.x;
    int base = (bh*LL + c*CT)*DH;
    for (int i = tid; i < CT*DH; i += 256) {
        qs[i/DH][i%DH] = g_qf[base + i];
        ks[i/DH][i%DH] = g_kf[base + i];
    }
    __syncthreads();
    int i  = tid >> 2;
    int e0 = (tid & 3) * 16;
    const float* Sp = g_S + (size_t)(bh*NC + c)*DH*DH;
    const float* zp = g_z + (bh*NC + c)*DH;
    const float* vg = g_vf + base;

    float acc[16] = {};
    float den = 1e-6f;
    for (int d = 0; d < DH; d++) {
        float qd = qs[i][d];
        den += qd * zp[d];
        const float* sr = Sp + d*DH + e0;
        #pragma unroll
        for (int u = 0; u < 16; u++) acc[u] += qd * sr[u];
    }
    for (int j = 0; j <= i; j++) {
        float s = 0.0f;
        #pragma unroll
        for (int d = 0; d < DH; d++) s += qs[i][d] * ks[j][d];
        den += s;
        const float* vr = vg + j*DH + e0;
        #pragma unroll
        for (int u = 0; u < 16; u++) acc[u] += s * vr[u];
    }
    int b = bh / HH, h = bh - b*HH;
    int l = c*CT + i;
    float* orow = g_attn + (size_t)(b*LL + l)*DD + h*DH + e0;
    float invd = 1.0f / den;
    #pragma unroll
    for (int u = 0; u < 16; u++) orow[u] = acc[u] * invd;
}

// ---------------- launch -----------------------------------------------------
extern "C" void kernel_launch(void* const* d_in, const int* in_sizes, int n_in,
                              void* d_out, int out_size) {
    const float* x          = (const float*)d_in[0];
    const float* W_qkv      = (const float*)d_in[1];
    const float* b_qkv      = (const float*)d_in[2];
    const float* W_sem_down = (const float*)d_in[3];
    const float* W_sem_up   = (const float*)d_in[4];
    const float* W_ctx_down = (const float*)d_in[5];
    const float* W_ctx_up   = (const float*)d_in[6];
    const float* temperature= (const float*)d_in[7];
    const float* W_proj     = (const float*)d_in[8];
    const float* b_proj     = (const float*)d_in[9];
    const float* gamma      = (const float*)d_in[10];
    const float* beta       = (const float*)d_in[11];
    float* y_out    = (float*)d_out;
    float* gate_out = y_out + (size_t)NROWS*DD;

    float *p_xn, *p_qkv, *p_hsem, *p_hctx, *p_sem, *p_ctx, *p_attn;
    cudaGetSymbolAddress((void**)&p_xn,   g_xn);
    cudaGetSymbolAddress((void**)&p_qkv,  g_qkv);
    cudaGetSymbolAddress((void**)&p_hsem, g_hsem);
    cudaGetSymbolAddress((void**)&p_hctx, g_hctx);
    cudaGetSymbolAddress((void**)&p_sem,  g_sem);
    cudaGetSymbolAddress((void**)&p_ctx,  g_ctx);
    cudaGetSymbolAddress((void**)&p_attn, g_attn);

    static bool attr_set = false;
    if (!attr_set) {
        cudaFuncSetAttribute(tgemm_kernel<0>, cudaFuncAttributeMaxDynamicSharedMemorySize, TGE_SMEM);
        cudaFuncSetAttribute(tgemm_kernel<1>, cudaFuncAttributeMaxDynamicSharedMemorySize, TGE_SMEM);
        cudaFuncSetAttribute(tgemm_kernel<2>, cudaFuncAttributeMaxDynamicSharedMemorySize, TGE_SMEM);
        attr_set = true;
    }

    ln_kernel<<<NROWS, 256>>>(x, gamma, beta);

    // qkv = xn @ W_qkv + b_qkv          (4096 x 2304 x 768)
    tgemm_kernel<1><<<dim3(3*DD/128, NROWS/128), 256, TGE_SMEM>>>(p_xn, W_qkv, b_qkv, p_qkv, 3*DD, DD);
    // low-rank (raw x input)            (4096 x 128 x 768) silu
    tgemm_kernel<2><<<dim3(RR/128,   NROWS/128), 256, TGE_SMEM>>>(x, W_sem_down, nullptr, p_hsem, RR, DD);
    tgemm_kernel<2><<<dim3(RR/128,   NROWS/128), 256, TGE_SMEM>>>(x, W_ctx_down, nullptr, p_hctx, RR, DD);
    // up                                (4096 x 1536 x 128)
    tgemm_kernel<0><<<dim3(2*DD/128, NROWS/128), 256, TGE_SMEM>>>(p_hsem, W_sem_up, nullptr, p_sem, 2*DD, RR);
    tgemm_kernel<0><<<dim3(2*DD/128, NROWS/128), 256, TGE_SMEM>>>(p_hctx, W_ctx_up, nullptr, p_ctx, 2*DD, RR);

    gate_kernel<<<(NROWS*DD)/256, 256>>>(temperature, gate_out);

    chunksum_kernel<<<dim3(NC, BHN), 256>>>();
    scan_kernel<<<BHN, 256>>>();
    attn_kernel<<<dim3(NC, BHN), 256>>>();

    // y = attn @ W_proj + b_proj        (4096 x 768 x 768)
    tgemm_kernel<1><<<dim3(DD/128, NROWS/128), 256, TGE_SMEM>>>(p_attn, W_proj, b_proj, y_out, DD, DD);
}

// round 5
// speedup vs baseline: 2.7023x; 1.1301x over previous
#include <cuda_runtime.h>
#include <math.h>
#include <stdint.h>

#define BB 2
#define LL 2048
#define DD 768
#define HH 12
#define RR 128
#define DH 64
#define NROWS (BB*LL)        // 4096
#define NC 32
#define CT 64
#define BHN (BB*HH)
#define PI_F 3.14159265358979323846f

// ---------------- scratch ---------------------------------------------------
__device__ float g_xn[NROWS*DD];
__device__ float g_qkv[NROWS*3*DD];
__device__ float g_hsem[NROWS*RR];
__device__ float g_hctx[NROWS*RR];
__device__ float g_sem[NROWS*2*DD];
__device__ float g_ctx[NROWS*2*DD];
__device__ float g_qf[NROWS*DD];
__device__ float g_kf[NROWS*DD];
__device__ float g_vf[NROWS*DD];
__device__ float g_S[BHN*NC*DH*DH];
__device__ float g_z[BHN*NC*DH];
__device__ float g_attn[NROWS*DD];

// ---------------- helpers ----------------------------------------------------
__device__ __forceinline__ uint32_t smem_u32(const void* p) {
    uint32_t a;
    asm("{ .reg .u64 t; cvta.to.shared.u64 t, %1; cvt.u32.u64 %0, t; }" : "=r"(a) : "l"(p));
    return a;
}
__device__ __forceinline__ void mma_tf32(float* c, const uint32_t* a,
                                         uint32_t b0, uint32_t b1) {
    asm volatile(
        "mma.sync.aligned.m16n8k8.row.col.f32.tf32.tf32.f32 "
        "{%0,%1,%2,%3}, {%4,%5,%6,%7}, {%8,%9}, {%0,%1,%2,%3};"
        : "+f"(c[0]), "+f"(c[1]), "+f"(c[2]), "+f"(c[3])
        : "r"(a[0]), "r"(a[1]), "r"(a[2]), "r"(a[3]), "r"(b0), "r"(b1));
}
__device__ __forceinline__ void cp16(uint32_t sp, const float* gp) {
    asm volatile("cp.async.cg.shared.global [%0], [%1], 16;" :: "r"(sp), "l"(gp) : "memory");
}
__device__ __forceinline__ float hi_of(float v) {
    return __uint_as_float(__float_as_uint(v) & 0xFFFFE000u);
}

// ---------------- TF32 mma.sync GEMM (raw smem, reg-split, cp.async) ---------
// C[M,N] = A[M,K] @ B[K,N] (+bias)(+silu). CTA 128x128, BK=32, 256 thr, 8 warps.
// blockIdx.z==1 switches to (A2,B2,C2) for fused independent GEMMs.
// EPI: 0=none, 1=bias, 2=silu
#define APAD 36
#define BPAD 136
#define STG_FLOATS (128*APAD + 32*BPAD)          // 4608 + 4352 = 8960
#define STG_BYTES (STG_FLOATS*4)                  // 35840
#define TGE_SMEM (2*STG_BYTES)                    // 71680

template<int EPI>
__global__ void __launch_bounds__(256, 2) tgemm_kernel(
    const float* __restrict__ A, const float* __restrict__ B,
    const float* __restrict__ bias, float* __restrict__ C,
    int N, int K,
    const float* __restrict__ A2, const float* __restrict__ B2,
    float* __restrict__ C2) {
    if (blockIdx.z == 1) {
        if (A2) A = A2;
        B = B2; C = C2;
    }
    extern __shared__ float sm[];
    uint32_t sbase = smem_u32(sm);
    int tid = threadIdx.x;
    int lane = tid & 31, wid = tid >> 5;
    int wm = wid & 3, wn = wid >> 2;
    int g = lane >> 2, t4 = lane & 3;
    int m0 = blockIdx.y * 128, n0 = blockIdx.x * 128;

    int arow[4], acol4[4], brow[4], bcol4[4];
    #pragma unroll
    for (int i = 0; i < 4; i++) {
        int idx = tid + i * 256;
        arow[i] = idx >> 3;  acol4[i] = idx & 7;   // A: 128 x 8 float4
        brow[i] = idx >> 5;  bcol4[i] = idx & 31;  // B: 32 x 32 float4
    }

    float c[2][8][4];
    #pragma unroll
    for (int mt = 0; mt < 2; mt++)
        #pragma unroll
        for (int nt = 0; nt < 8; nt++)
            #pragma unroll
            for (int r = 0; r < 4; r++) c[mt][nt][r] = 0.0f;

    int nstages = K >> 5;

    // --- stage issue (cp.async) ---
    auto issue = [&](int s, int buf) {
        int k0 = s << 5;
        uint32_t so = sbase + buf * STG_BYTES;
        #pragma unroll
        for (int i = 0; i < 4; i++) {
            cp16(so + (arow[i] * APAD + acol4[i] * 4) * 4,
                 A + (size_t)(m0 + arow[i]) * K + k0 + acol4[i] * 4);
        }
        #pragma unroll
        for (int i = 0; i < 4; i++) {
            cp16(so + (128 * APAD + brow[i] * BPAD + bcol4[i] * 4) * 4,
                 B + (size_t)(k0 + brow[i]) * N + n0 + bcol4[i] * 4);
        }
        asm volatile("cp.async.commit_group;" ::: "memory");
    };

    issue(0, 0);
    for (int s = 0; s < nstages; s++) {
        int buf = s & 1;
        if (s + 1 < nstages) {
            issue(s + 1, buf ^ 1);
            asm volatile("cp.async.wait_group 1;" ::: "memory");
        } else {
            asm volatile("cp.async.wait_group 0;" ::: "memory");
        }
        __syncthreads();

        const float* smA = sm + buf * STG_FLOATS;
        const float* smB = smA + 128 * APAD;

        #pragma unroll
        for (int ks = 0; ks < 4; ks++) {
            int kb = ks * 8;
            uint32_t ah[2][4], al[2][4];
            #pragma unroll
            for (int mt = 0; mt < 2; mt++) {
                int r0 = wm * 32 + mt * 16;
                float a0 = smA[(r0 + g    ) * APAD + kb + t4    ];
                float a1 = smA[(r0 + g + 8) * APAD + kb + t4    ];
                float a2 = smA[(r0 + g    ) * APAD + kb + t4 + 4];
                float a3 = smA[(r0 + g + 8) * APAD + kb + t4 + 4];
                float h0 = hi_of(a0), h1 = hi_of(a1), h2 = hi_of(a2), h3 = hi_of(a3);
                ah[mt][0] = __float_as_uint(h0); al[mt][0] = __float_as_uint(a0 - h0);
                ah[mt][1] = __float_as_uint(h1); al[mt][1] = __float_as_uint(a1 - h1);
                ah[mt][2] = __float_as_uint(h2); al[mt][2] = __float_as_uint(a2 - h2);
                ah[mt][3] = __float_as_uint(h3); al[mt][3] = __float_as_uint(a3 - h3);
            }
            #pragma unroll
            for (int nt = 0; nt < 8; nt++) {
                int nb = wn * 64 + nt * 8 + g;
                float b0 = smB[(kb + t4    ) * BPAD + nb];
                float b1 = smB[(kb + t4 + 4) * BPAD + nb];
                float hb0 = hi_of(b0), hb1 = hi_of(b1);
                uint32_t bh0 = __float_as_uint(hb0), bh1 = __float_as_uint(hb1);
                uint32_t bl0 = __float_as_uint(b0 - hb0), bl1 = __float_as_uint(b1 - hb1);
                #pragma unroll
                for (int mt = 0; mt < 2; mt++) {
                    mma_tf32(c[mt][nt], ah[mt], bh0, bh1);
                    mma_tf32(c[mt][nt], ah[mt], bl0, bl1);
                    mma_tf32(c[mt][nt], al[mt], bh0, bh1);
                }
            }
        }
        __syncthreads();
    }

    // ---- epilogue ----
    #pragma unroll
    for (int mt = 0; mt < 2; mt++) {
        int row = m0 + wm * 32 + mt * 16 + g;
        #pragma unroll
        for (int nt = 0; nt < 8; nt++) {
            int col = n0 + wn * 64 + nt * 8 + 2 * t4;
            float v0 = c[mt][nt][0], v1 = c[mt][nt][1];
            float v2 = c[mt][nt][2], v3 = c[mt][nt][3];
            if (EPI == 1) {
                float b0 = bias[col], b1 = bias[col + 1];
                v0 += b0; v1 += b1; v2 += b0; v3 += b1;
            }
            if (EPI == 2) {
                v0 = v0 / (1.0f + expf(-v0));
                v1 = v1 / (1.0f + expf(-v1));
                v2 = v2 / (1.0f + expf(-v2));
                v3 = v3 / (1.0f + expf(-v3));
            }
            *(float2*)(C + (size_t)row * N + col)       = make_float2(v0, v1);
            *(float2*)(C + (size_t)(row + 8) * N + col) = make_float2(v2, v3);
        }
    }
}

// ---------------- layernorm -------------------------------------------------
__global__ void ln_kernel(const float* __restrict__ x,
                          const float* __restrict__ gamma,
                          const float* __restrict__ beta) {
    int row = blockIdx.x;
    const float* xr = x + row*DD;
    int t = threadIdx.x;
    float v0 = xr[t], v1 = xr[t+256], v2 = xr[t+512];
    __shared__ float red[256], red2[256];
    red[t]  = v0+v1+v2;
    red2[t] = v0*v0+v1*v1+v2*v2;
    __syncthreads();
    for (int o = 128; o > 0; o >>= 1) {
        if (t < o) { red[t] += red[t+o]; red2[t] += red2[t+o]; }
        __syncthreads();
    }
    float mu  = red[0] * (1.0f/DD);
    float var = red2[0] * (1.0f/DD) - mu*mu;
    float inv = rsqrtf(var + 1e-5f);
    float* o = g_xn + row*DD;
    o[t]     = (v0-mu)*inv*gamma[t]     + beta[t];
    o[t+256] = (v1-mu)*inv*gamma[t+256] + beta[t+256];
    o[t+512] = (v2-mu)*inv*gamma[t+512] + beta[t+512];
}

// ---------------- gate + feature map + head reshape -------------------------
__device__ __forceinline__ float softplus_f(float a) {
    return a > 20.0f ? a : log1pf(expf(a));
}
__global__ void gate_kernel(const float* __restrict__ temperature,
                            float* __restrict__ gate_out) {
    int idx = blockIdx.x*256 + threadIdx.x;
    int row = idx / DD, d = idx - row*DD;
    const float* sr = g_sem + row*(2*DD);
    const float* cr = g_ctx + row*(2*DD);
    float sa = softplus_f(sr[d]);
    float sp = tanhf(sr[DD + d]) * PI_F;
    float ca = softplus_f(cr[d]);
    float cp = tanhf(cr[DD + d]) * PI_F;
    float inter = sa * ca * cosf(sp - cp) * temperature[0];
    float gate = 1.0f / (1.0f + expf(-inter));
    gate_out[idx] = gate;

    const float* qr = g_qkv + row*(3*DD);
    float q = qr[d];
    float k = qr[DD + d] * (1.0f + gate);
    float v = qr[2*DD + d];
    float qfv = q > 0.0f ? q + 1.0f : expf(q);
    float kfv = k > 0.0f ? k + 1.0f : expf(k);
    int b = row / LL, l = row - b*LL;
    int h = d / DH, dh = d - h*DH;
    int hid = ((b*HH + h)*LL + l)*DH + dh;
    g_qf[hid] = qfv;
    g_kf[hid] = kfv;
    g_vf[hid] = v;
}

// ---------------- chunked linear attention ----------------------------------
__global__ void chunksum_kernel() {
    int c  = blockIdx.x;
    int bh = blockIdx.y;
    __shared__ float ks[CT][DH];
    __shared__ float vs[CT][DH];
    int tid = threadIdx.x;
    int base = (bh*LL + c*CT)*DH;
    for (int i = tid; i < CT*DH; i += 256) {
        ks[i/DH][i%DH] = g_kf[base + i];
        vs[i/DH][i%DH] = g_vf[base + i];
    }
    __syncthreads();
    int d  = tid >> 2;
    int e0 = (tid & 3) * 16;
    float acc[16] = {};
    float zacc = 0.0f;
    for (int l = 0; l < CT; l++) {
        float kd = ks[l][d];
        zacc += kd;
        #pragma unroll
        for (int u = 0; u < 16; u++) acc[u] += kd * vs[l][e0 + u];
    }
    float* Sp = g_S + (size_t)(bh*NC + c)*DH*DH;
    #pragma unroll
    for (int u = 0; u < 16; u++) Sp[d*DH + e0 + u] = acc[u];
    if ((tid & 3) == 0) g_z[(bh*NC + c)*DH + d] = zacc;
}

__global__ void scan_kernel() {
    int bh = blockIdx.x;
    int tid = threadIdx.x;
    for (int e = tid; e < DH*DH; e += 256) {
        float run = 0.0f;
        for (int c = 0; c < NC; c++) {
            float* p = g_S + (size_t)(bh*NC + c)*DH*DH + e;
            float t = *p; *p = run; run += t;
        }
    }
    if (tid < DH) {
        float run = 0.0f;
        for (int c = 0; c < NC; c++) {
            float* p = g_z + (bh*NC + c)*DH + tid;
            float t = *p; *p = run; run += t;
        }
    }
}

__global__ void attn_kernel() {
    int c  = blockIdx.x;
    int bh = blockIdx.y;
    __shared__ float qs[CT][DH+1];
    __shared__ float ks[CT][DH+1];
    int tid = threadIdx.x;
    int base = (bh*LL + c*CT)*DH;
    for (int i = tid; i < CT*DH; i += 256) {
        qs[i/DH][i%DH] = g_qf[base + i];
        ks[i/DH][i%DH] = g_kf[base + i];
    }
    __syncthreads();
    int i  = tid >> 2;
    int e0 = (tid & 3) * 16;
    const float* Sp = g_S + (size_t)(bh*NC + c)*DH*DH;
    const float* zp = g_z + (bh*NC + c)*DH;
    const float* vg = g_vf + base;

    float acc[16] = {};
    float den = 1e-6f;
    for (int d = 0; d < DH; d++) {
        float qd = qs[i][d];
        den += qd * zp[d];
        const float* sr = Sp + d*DH + e0;
        #pragma unroll
        for (int u = 0; u < 16; u++) acc[u] += qd * sr[u];
    }
    for (int j = 0; j <= i; j++) {
        float s = 0.0f;
        #pragma unroll
        for (int d = 0; d < DH; d++) s += qs[i][d] * ks[j][d];
        den += s;
        const float* vr = vg + j*DH + e0;
        #pragma unroll
        for (int u = 0; u < 16; u++) acc[u] += s * vr[u];
    }
    int b = bh / HH, h = bh - b*HH;
    int l = c*CT + i;
    float* orow = g_attn + (size_t)(b*LL + l)*DD + h*DH + e0;
    float invd = 1.0f / den;
    #pragma unroll
    for (int u = 0; u < 16; u++) orow[u] = acc[u] * invd;
}

// ---------------- launch -----------------------------------------------------
extern "C" void kernel_launch(void* const* d_in, const int* in_sizes, int n_in,
                              void* d_out, int out_size) {
    const float* x          = (const float*)d_in[0];
    const float* W_qkv      = (const float*)d_in[1];
    const float* b_qkv      = (const float*)d_in[2];
    const float* W_sem_down = (const float*)d_in[3];
    const float* W_sem_up   = (const float*)d_in[4];
    const float* W_ctx_down = (const float*)d_in[5];
    const float* W_ctx_up   = (const float*)d_in[6];
    const float* temperature= (const float*)d_in[7];
    const float* W_proj     = (const float*)d_in[8];
    const float* b_proj     = (const float*)d_in[9];
    const float* gamma      = (const float*)d_in[10];
    const float* beta       = (const float*)d_in[11];
    float* y_out    = (float*)d_out;
    float* gate_out = y_out + (size_t)NROWS*DD;

    float *p_xn, *p_qkv, *p_hsem, *p_hctx, *p_sem, *p_ctx, *p_attn;
    cudaGetSymbolAddress((void**)&p_xn,   g_xn);
    cudaGetSymbolAddress((void**)&p_qkv,  g_qkv);
    cudaGetSymbolAddress((void**)&p_hsem, g_hsem);
    cudaGetSymbolAddress((void**)&p_hctx, g_hctx);
    cudaGetSymbolAddress((void**)&p_sem,  g_sem);
    cudaGetSymbolAddress((void**)&p_ctx,  g_ctx);
    cudaGetSymbolAddress((void**)&p_attn, g_attn);

    static bool attr_set = false;
    if (!attr_set) {
        cudaFuncSetAttribute(tgemm_kernel<0>, cudaFuncAttributeMaxDynamicSharedMemorySize, TGE_SMEM);
        cudaFuncSetAttribute(tgemm_kernel<1>, cudaFuncAttributeMaxDynamicSharedMemorySize, TGE_SMEM);
        cudaFuncSetAttribute(tgemm_kernel<2>, cudaFuncAttributeMaxDynamicSharedMemorySize, TGE_SMEM);
        attr_set = true;
    }

    ln_kernel<<<NROWS, 256>>>(x, gamma, beta);

    // qkv = xn @ W_qkv + b_qkv          (4096 x 2304 x 768)
    tgemm_kernel<1><<<dim3(3*DD/128, NROWS/128, 1), 256, TGE_SMEM>>>(
        p_xn, W_qkv, b_qkv, p_qkv, 3*DD, DD, nullptr, nullptr, nullptr);
    // fused down-projections (silu): z=0 sem, z=1 ctx   (4096 x 128 x 768)
    tgemm_kernel<2><<<dim3(RR/128, NROWS/128, 2), 256, TGE_SMEM>>>(
        x, W_sem_down, nullptr, p_hsem, RR, DD, nullptr, W_ctx_down, p_hctx);
    // fused up-projections: z=0 sem, z=1 ctx            (4096 x 1536 x 128)
    tgemm_kernel<0><<<dim3(2*DD/128, NROWS/128, 2), 256, TGE_SMEM>>>(
        p_hsem, W_sem_up, nullptr, p_sem, 2*DD, RR, p_hctx, W_ctx_up, p_ctx);

    gate_kernel<<<(NROWS*DD)/256, 256>>>(temperature, gate_out);

    chunksum_kernel<<<dim3(NC, BHN), 256>>>();
    scan_kernel<<<BHN, 256>>>();
    attn_kernel<<<dim3(NC, BHN), 256>>>();

    // y = attn @ W_proj + b_proj        (4096 x 768 x 768)
    tgemm_kernel<1><<<dim3(DD/128, NROWS/128, 1), 256, TGE_SMEM>>>(
        p_attn, W_proj, b_proj, y_out, DD, DD, nullptr, nullptr, nullptr);
}

// round 6
// speedup vs baseline: 3.2986x; 1.2206x over previous
#include <cuda_runtime.h>
#include <cuda_bf16.h>
#include <math.h>
#include <stdint.h>

#define BB 2
#define LL 2048
#define DD 768
#define HH 12
#define RR 128
#define DH 64
#define NROWS (BB*LL)        // 4096
#define NC 32
#define CT 64
#define BHN (BB*HH)
#define PI_F 3.14159265358979323846f

typedef __nv_bfloat16 bf16;

// ---------------- scratch ---------------------------------------------------
__device__ float g_qkv[NROWS*3*DD];
__device__ float g_sem[NROWS*2*DD];
__device__ float g_ctx[NROWS*2*DD];
__device__ float g_qf[NROWS*DD];
__device__ float g_kf[NROWS*DD];
__device__ float g_vf[NROWS*DD];
__device__ float g_S[BHN*NC*DH*DH];
__device__ float g_z[BHN*NC*DH];

// bf16 split pairs
__device__ bf16 g_xn0[NROWS*DD], g_xn1[NROWS*DD];
__device__ bf16 g_x0[NROWS*DD],  g_x1[NROWS*DD];
__device__ bf16 g_hs0[NROWS*RR], g_hs1[NROWS*RR];
__device__ bf16 g_hc0[NROWS*RR], g_hc1[NROWS*RR];
__device__ bf16 g_at0[NROWS*DD], g_at1[NROWS*DD];
// weights, split + transposed to [N][K]
__device__ bf16 g_wq0[3*DD*DD],  g_wq1[3*DD*DD];
__device__ bf16 g_wsd0[RR*DD],   g_wsd1[RR*DD];
__device__ bf16 g_wcd0[RR*DD],   g_wcd1[RR*DD];
__device__ bf16 g_wsu0[2*DD*RR], g_wsu1[2*DD*RR];
__device__ bf16 g_wcu0[2*DD*RR], g_wcu1[2*DD*RR];
__device__ bf16 g_wp0[DD*DD],    g_wp1[DD*DD];

// ---------------- helpers ----------------------------------------------------
__device__ __forceinline__ uint32_t smem_u32p(const void* p) {
    uint32_t a;
    asm("{ .reg .u64 t; cvta.to.shared.u64 t, %1; cvt.u32.u64 %0, t; }" : "=r"(a) : "l"(p));
    return a;
}
__device__ __forceinline__ void mma_bf16(float* c, const uint32_t* a,
                                         uint32_t b0, uint32_t b1) {
    asm volatile(
        "mma.sync.aligned.m16n8k16.row.col.f32.bf16.bf16.f32 "
        "{%0,%1,%2,%3}, {%4,%5,%6,%7}, {%8,%9}, {%0,%1,%2,%3};"
        : "+f"(c[0]), "+f"(c[1]), "+f"(c[2]), "+f"(c[3])
        : "r"(a[0]), "r"(a[1]), "r"(a[2]), "r"(a[3]), "r"(b0), "r"(b1));
}
__device__ __forceinline__ void cp16(uint32_t sp, const void* gp) {
    asm volatile("cp.async.cg.shared.global [%0], [%1], 16;" :: "r"(sp), "l"(gp) : "memory");
}
__device__ __forceinline__ void split2(float v, bf16& h, bf16& l) {
    h = __float2bfloat16(v);
    l = __float2bfloat16(v - __bfloat162float(h));
}

// ---------------- split-bf16 GEMM (3-term, m16n8k16) -------------------------
// C[M,N] = (A0+A1)[M,K] @ (B0+B1)^T[N,K].  CTA 128x128, BK=32, 256 thr.
// blockIdx.z==1 switches to the secondary operand set (fused independent GEMMs).
// EPI: 0=plain fp32 out, 1=bias fp32 out, 2=silu + split bf16 pair out
#define ST32 20                         // u32 row stride (80B, 16B-aligned, conflict-free)
#define MAT_U32 (128*ST32)              // 2560
#define STAGE_U32 (4*MAT_U32)           // 10240
#define TGE_SMEM (2*STAGE_U32*4)        // 81920 bytes

template<int EPI>
__global__ void __launch_bounds__(256, 2) bgemm_kernel(
    const bf16* __restrict__ A0, const bf16* __restrict__ A1,
    const bf16* __restrict__ B0, const bf16* __restrict__ B1,
    const float* __restrict__ bias, float* __restrict__ Cf,
    bf16* __restrict__ C0, bf16* __restrict__ C1,
    int N, int K,
    const bf16* A0b, const bf16* A1b, const bf16* B0b, const bf16* B1b,
    float* Cfb, bf16* C0b, bf16* C1b) {
    if (blockIdx.z == 1) {
        if (A0b) { A0 = A0b; A1 = A1b; }
        B0 = B0b; B1 = B1b; Cf = Cfb; C0 = C0b; C1 = C1b;
    }
    extern __shared__ uint32_t smu[];
    uint32_t sbase = smem_u32p(smu);
    int tid = threadIdx.x;
    int lane = tid & 31, wid = tid >> 5;
    int wm = wid & 3, wn = wid >> 2;
    int g = lane >> 2, t4 = lane & 3;
    int m0 = blockIdx.y * 128, n0 = blockIdx.x * 128;

    float c[2][8][4];
    #pragma unroll
    for (int mt = 0; mt < 2; mt++)
        #pragma unroll
        for (int nt = 0; nt < 8; nt++)
            #pragma unroll
            for (int r = 0; r < 4; r++) c[mt][nt][r] = 0.0f;

    int nstages = K >> 5;

    auto issue = [&](int s, int buf) {
        int k0 = s << 5;
        uint32_t so = sbase + buf * (STAGE_U32 * 4);
        #pragma unroll
        for (int i = 0; i < 2; i++) {
            int ch = tid + i * 256;            // 0..511
            int row = ch >> 2, q = ch & 3;
            uint32_t d = so + (row * ST32 + q * 4) * 4;
            cp16(d,                   A0 + (size_t)(m0 + row) * K + k0 + q * 8);
            cp16(d + MAT_U32 * 4,     A1 + (size_t)(m0 + row) * K + k0 + q * 8);
            cp16(d + 2 * MAT_U32 * 4, B0 + (size_t)(n0 + row) * K + k0 + q * 8);
            cp16(d + 3 * MAT_U32 * 4, B1 + (size_t)(n0 + row) * K + k0 + q * 8);
        }
        asm volatile("cp.async.commit_group;" ::: "memory");
    };

    issue(0, 0);
    for (int s = 0; s < nstages; s++) {
        int buf = s & 1;
        if (s + 1 < nstages) {
            issue(s + 1, buf ^ 1);
            asm volatile("cp.async.wait_group 1;" ::: "memory");
        } else {
            asm volatile("cp.async.wait_group 0;" ::: "memory");
        }
        __syncthreads();

        const uint32_t* sA0 = smu + buf * STAGE_U32;
        const uint32_t* sA1 = sA0 + MAT_U32;
        const uint32_t* sB0 = sA1 + MAT_U32;
        const uint32_t* sB1 = sB0 + MAT_U32;

        #pragma unroll
        for (int ks = 0; ks < 2; ks++) {
            int kb = ks * 8;
            uint32_t a0f[2][4], a1f[2][4];
            #pragma unroll
            for (int mt = 0; mt < 2; mt++) {
                int r = wm * 32 + mt * 16 + g;
                a0f[mt][0] = sA0[r * ST32 + kb + t4];
                a0f[mt][1] = sA0[(r + 8) * ST32 + kb + t4];
                a0f[mt][2] = sA0[r * ST32 + kb + t4 + 4];
                a0f[mt][3] = sA0[(r + 8) * ST32 + kb + t4 + 4];
                a1f[mt][0] = sA1[r * ST32 + kb + t4];
                a1f[mt][1] = sA1[(r + 8) * ST32 + kb + t4];
                a1f[mt][2] = sA1[r * ST32 + kb + t4 + 4];
                a1f[mt][3] = sA1[(r + 8) * ST32 + kb + t4 + 4];
            }
            #pragma unroll
            for (int nt = 0; nt < 8; nt++) {
                int n = wn * 64 + nt * 8 + g;
                uint32_t b00 = sB0[n * ST32 + kb + t4];
                uint32_t b01 = sB0[n * ST32 + kb + t4 + 4];
                uint32_t b10 = sB1[n * ST32 + kb + t4];
                uint32_t b11 = sB1[n * ST32 + kb + t4 + 4];
                #pragma unroll
                for (int mt = 0; mt < 2; mt++) {
                    mma_bf16(c[mt][nt], a0f[mt], b00, b01);   // A0*B0
                    mma_bf16(c[mt][nt], a0f[mt], b10, b11);   // A0*B1
                    mma_bf16(c[mt][nt], a1f[mt], b00, b01);   // A1*B0
                }
            }
        }
        __syncthreads();
    }

    // ---- epilogue ----
    #pragma unroll
    for (int mt = 0; mt < 2; mt++) {
        int row = m0 + wm * 32 + mt * 16 + g;
        #pragma unroll
        for (int nt = 0; nt < 8; nt++) {
            int col = n0 + wn * 64 + nt * 8 + 2 * t4;
            float v0 = c[mt][nt][0], v1 = c[mt][nt][1];
            float v2 = c[mt][nt][2], v3 = c[mt][nt][3];
            if (EPI == 1) {
                float b0 = bias[col], b1 = bias[col + 1];
                v0 += b0; v1 += b1; v2 += b0; v3 += b1;
            }
            if (EPI == 2) {
                v0 = v0 / (1.0f + expf(-v0));
                v1 = v1 / (1.0f + expf(-v1));
                v2 = v2 / (1.0f + expf(-v2));
                v3 = v3 / (1.0f + expf(-v3));
                bf16 h0, l0, h1, l1, h2, l2, h3, l3;
                split2(v0, h0, l0); split2(v1, h1, l1);
                split2(v2, h2, l2); split2(v3, h3, l3);
                __nv_bfloat162 ph0; ph0.x = h0; ph0.y = h1;
                __nv_bfloat162 pl0; pl0.x = l0; pl0.y = l1;
                __nv_bfloat162 ph1; ph1.x = h2; ph1.y = h3;
                __nv_bfloat162 pl1; pl1.x = l2; pl1.y = l3;
                *(__nv_bfloat162*)(C0 + (size_t)row * N + col)       = ph0;
                *(__nv_bfloat162*)(C1 + (size_t)row * N + col)       = pl0;
                *(__nv_bfloat162*)(C0 + (size_t)(row + 8) * N + col) = ph1;
                *(__nv_bfloat162*)(C1 + (size_t)(row + 8) * N + col) = pl1;
            } else {
                *(float2*)(Cf + (size_t)row * N + col)       = make_float2(v0, v1);
                *(float2*)(Cf + (size_t)(row + 8) * N + col) = make_float2(v2, v3);
            }
        }
    }
}

// ---------------- weight split + transpose -----------------------------------
// W[K][N] fp32  ->  W0t,W1t [N][K] bf16 pair.  32x32 tiles via smem.
#define TQ  1728
#define TSD (TQ + 96)
#define TCD (TSD + 96)
#define TSU (TCD + 192)
#define TCU (TSU + 192)
#define TP  (TCU + 576)
__global__ void wsplit_kernel(
    const float* __restrict__ Wq, const float* __restrict__ Wsd,
    const float* __restrict__ Wcd, const float* __restrict__ Wsu,
    const float* __restrict__ Wcu, const float* __restrict__ Wp) {
    int t = blockIdx.x;
    const float* W; bf16 *D0, *D1; int K, N;
    if (t < TQ)       { W = Wq;  D0 = g_wq0;  D1 = g_wq1;  K = DD;  N = 3*DD; }
    else if (t < TSD) { t -= TQ;  W = Wsd; D0 = g_wsd0; D1 = g_wsd1; K = DD;  N = RR; }
    else if (t < TCD) { t -= TSD; W = Wcd; D0 = g_wcd0; D1 = g_wcd1; K = DD;  N = RR; }
    else if (t < TSU) { t -= TCD; W = Wsu; D0 = g_wsu0; D1 = g_wsu1; K = RR;  N = 2*DD; }
    else if (t < TCU) { t -= TSU; W = Wcu; D0 = g_wcu0; D1 = g_wcu1; K = RR;  N = 2*DD; }
    else              { t -= TCU; W = Wp;  D0 = g_wp0;  D1 = g_wp1;  K = DD;  N = DD; }
    int tN = N >> 5;
    int k0 = (t / tN) << 5, n0 = (t % tN) << 5;
    __shared__ float sm[32][33];
    int tx = threadIdx.x & 31, ty = threadIdx.x >> 5;   // 256 threads
    #pragma unroll
    for (int i = 0; i < 4; i++)
        sm[ty + 8*i][tx] = W[(size_t)(k0 + ty + 8*i) * N + n0 + tx];
    __syncthreads();
    #pragma unroll
    for (int i = 0; i < 4; i++) {
        float v = sm[tx][ty + 8*i];
        bf16 h, l; split2(v, h, l);
        size_t o = (size_t)(n0 + ty + 8*i) * K + k0 + tx;
        D0[o] = h; D1[o] = l;
    }
}

// ---------------- layernorm + input splits -----------------------------------
__global__ void ln_kernel(const float* __restrict__ x,
                          const float* __restrict__ gamma,
                          const float* __restrict__ beta) {
    int row = blockIdx.x;
    const float* xr = x + (size_t)row*DD;
    int t = threadIdx.x;
    float v0 = xr[t], v1 = xr[t+256], v2 = xr[t+512];
    __shared__ float red[256], red2[256];
    red[t]  = v0+v1+v2;
    red2[t] = v0*v0+v1*v1+v2*v2;
    __syncthreads();
    for (int o = 128; o > 0; o >>= 1) {
        if (t < o) { red[t] += red[t+o]; red2[t] += red2[t+o]; }
        __syncthreads();
    }
    float mu  = red[0] * (1.0f/DD);
    float var = red2[0] * (1.0f/DD) - mu*mu;
    float inv = rsqrtf(var + 1e-5f);
    size_t base = (size_t)row*DD;
    float vv[3] = {v0, v1, v2};
    #pragma unroll
    for (int i = 0; i < 3; i++) {
        int d = t + i*256;
        float xn = (vv[i]-mu)*inv*gamma[d] + beta[d];
        bf16 h, l;
        split2(xn, h, l);    g_xn0[base+d] = h; g_xn1[base+d] = l;
        split2(vv[i], h, l); g_x0[base+d]  = h; g_x1[base+d]  = l;
    }
}

// ---------------- gate + feature map + head reshape ---------------------------
__device__ __forceinline__ float softplus_f(float a) {
    return a > 20.0f ? a : log1pf(expf(a));
}
__global__ void gate_kernel(const float* __restrict__ temperature,
                            float* __restrict__ gate_out) {
    int idx = blockIdx.x*256 + threadIdx.x;
    int row = idx / DD, d = idx - row*DD;
    const float* sr = g_sem + (size_t)row*(2*DD);
    const float* cr = g_ctx + (size_t)row*(2*DD);
    float sa = softplus_f(sr[d]);
    float sp = tanhf(sr[DD + d]) * PI_F;
    float ca = softplus_f(cr[d]);
    float cp = tanhf(cr[DD + d]) * PI_F;
    float inter = sa * ca * cosf(sp - cp) * temperature[0];
    float gate = 1.0f / (1.0f + expf(-inter));
    gate_out[idx] = gate;

    const float* qr = g_qkv + (size_t)row*(3*DD);
    float q = qr[d];
    float k = qr[DD + d] * (1.0f + gate);
    float v = qr[2*DD + d];
    float qfv = q > 0.0f ? q + 1.0f : expf(q);
    float kfv = k > 0.0f ? k + 1.0f : expf(k);
    int b = row / LL, l = row - b*LL;
    int h = d / DH, dh = d - h*DH;
    int hid = ((b*HH + h)*LL + l)*DH + dh;
    g_qf[hid] = qfv;
    g_kf[hid] = kfv;
    g_vf[hid] = v;
}

// ---------------- chunked linear attention ------------------------------------
__global__ void chunksum_kernel() {
    int c  = blockIdx.x;
    int bh = blockIdx.y;
    __shared__ float ks[CT][DH];
    __shared__ float vs[CT][DH];
    int tid = threadIdx.x;
    int base = (bh*LL + c*CT)*DH;
    for (int i = tid; i < CT*DH; i += 256) {
        ks[i/DH][i%DH] = g_kf[base + i];
        vs[i/DH][i%DH] = g_vf[base + i];
    }
    __syncthreads();
    int d  = tid >> 2;
    int e0 = (tid & 3) * 16;
    float acc[16] = {};
    float zacc = 0.0f;
    for (int l = 0; l < CT; l++) {
        float kd = ks[l][d];
        zacc += kd;
        #pragma unroll
        for (int u = 0; u < 16; u++) acc[u] += kd * vs[l][e0 + u];
    }
    float* Sp = g_S + (size_t)(bh*NC + c)*DH*DH;
    #pragma unroll
    for (int u = 0; u < 16; u++) Sp[d*DH + e0 + u] = acc[u];
    if ((tid & 3) == 0) g_z[(bh*NC + c)*DH + d] = zacc;
}

__global__ void scan_kernel() {
    int bh = blockIdx.x;
    int tid = threadIdx.x;
    for (int e = tid; e < DH*DH; e += 256) {
        float run = 0.0f;
        for (int c = 0; c < NC; c++) {
            float* p = g_S + (size_t)(bh*NC + c)*DH*DH + e;
            float t = *p; *p = run; run += t;
        }
    }
    if (tid < DH) {
        float run = 0.0f;
        for (int c = 0; c < NC; c++) {
            float* p = g_z + (bh*NC + c)*DH + tid;
            float t = *p; *p = run; run += t;
        }
    }
}

__global__ void attn_kernel() {
    int c  = blockIdx.x;
    int bh = blockIdx.y;
    __shared__ float qs[CT][DH+1];
    __shared__ float ks[CT][DH+1];
    int tid = threadIdx.x;
    int base = (bh*LL + c*CT)*DH;
    for (int i = tid; i < CT*DH; i += 256) {
        qs[i/DH][i%DH] = g_qf[base + i];
        ks[i/DH][i%DH] = g_kf[base + i];
    }
    __syncthreads();
    int i  = tid >> 2;
    int e0 = (tid & 3) * 16;
    const float* Sp = g_S + (size_t)(bh*NC + c)*DH*DH;
    const float* zp = g_z + (bh*NC + c)*DH;
    const float* vg = g_vf + base;

    float acc[16] = {};
    float den = 1e-6f;
    for (int d = 0; d < DH; d++) {
        float qd = qs[i][d];
        den += qd * zp[d];
        const float* sr = Sp + d*DH + e0;
        #pragma unroll
        for (int u = 0; u < 16; u++) acc[u] += qd * sr[u];
    }
    for (int j = 0; j <= i; j++) {
        float s = 0.0f;
        #pragma unroll
        for (int d = 0; d < DH; d++) s += qs[i][d] * ks[j][d];
        den += s;
        const float* vr = vg + j*DH + e0;
        #pragma unroll
        for (int u = 0; u < 16; u++) acc[u] += s * vr[u];
    }
    int b = bh / HH, h = bh - b*HH;
    int l = c*CT + i;
    size_t obase = (size_t)(b*LL + l)*DD + h*DH + e0;
    float invd = 1.0f / den;
    #pragma unroll
    for (int u = 0; u < 16; u += 2) {
        float o0 = acc[u] * invd, o1 = acc[u+1] * invd;
        bf16 h0, l0, h1, l1;
        split2(o0, h0, l0); split2(o1, h1, l1);
        __nv_bfloat162 ph; ph.x = h0; ph.y = h1;
        __nv_bfloat162 pl; pl.x = l0; pl.y = l1;
        *(__nv_bfloat162*)(g_at0 + obase + u) = ph;
        *(__nv_bfloat162*)(g_at1 + obase + u) = pl;
    }
}

// ---------------- launch -------------------------------------------------------
extern "C" void kernel_launch(void* const* d_in, const int* in_sizes, int n_in,
                              void* d_out, int out_size) {
    const float* x          = (const float*)d_in[0];
    const float* W_qkv      = (const float*)d_in[1];
    const float* b_qkv      = (const float*)d_in[2];
    const float* W_sem_down = (const float*)d_in[3];
    const float* W_sem_up   = (const float*)d_in[4];
    const float* W_ctx_down = (const float*)d_in[5];
    const float* W_ctx_up   = (const float*)d_in[6];
    const float* temperature= (const float*)d_in[7];
    const float* W_proj     = (const float*)d_in[8];
    const float* b_proj     = (const float*)d_in[9];
    const float* gamma      = (const float*)d_in[10];
    const float* beta       = (const float*)d_in[11];
    float* y_out    = (float*)d_out;
    float* gate_out = y_out + (size_t)NROWS*DD;

    float *p_qkv, *p_sem, *p_ctx;
    bf16 *p_xn0, *p_xn1, *p_x0, *p_x1, *p_hs0, *p_hs1, *p_hc0, *p_hc1, *p_at0, *p_at1;
    bf16 *p_wq0, *p_wq1, *p_wsd0, *p_wsd1, *p_wcd0, *p_wcd1;
    bf16 *p_wsu0, *p_wsu1, *p_wcu0, *p_wcu1, *p_wp0, *p_wp1;
    cudaGetSymbolAddress((void**)&p_qkv, g_qkv);
    cudaGetSymbolAddress((void**)&p_sem, g_sem);
    cudaGetSymbolAddress((void**)&p_ctx, g_ctx);
    cudaGetSymbolAddress((void**)&p_xn0, g_xn0);  cudaGetSymbolAddress((void**)&p_xn1, g_xn1);
    cudaGetSymbolAddress((void**)&p_x0,  g_x0);   cudaGetSymbolAddress((void**)&p_x1,  g_x1);
    cudaGetSymbolAddress((void**)&p_hs0, g_hs0);  cudaGetSymbolAddress((void**)&p_hs1, g_hs1);
    cudaGetSymbolAddress((void**)&p_hc0, g_hc0);  cudaGetSymbolAddress((void**)&p_hc1, g_hc1);
    cudaGetSymbolAddress((void**)&p_at0, g_at0);  cudaGetSymbolAddress((void**)&p_at1, g_at1);
    cudaGetSymbolAddress((void**)&p_wq0, g_wq0);  cudaGetSymbolAddress((void**)&p_wq1, g_wq1);
    cudaGetSymbolAddress((void**)&p_wsd0,g_wsd0); cudaGetSymbolAddress((void**)&p_wsd1,g_wsd1);
    cudaGetSymbolAddress((void**)&p_wcd0,g_wcd0); cudaGetSymbolAddress((void**)&p_wcd1,g_wcd1);
    cudaGetSymbolAddress((void**)&p_wsu0,g_wsu0); cudaGetSymbolAddress((void**)&p_wsu1,g_wsu1);
    cudaGetSymbolAddress((void**)&p_wcu0,g_wcu0); cudaGetSymbolAddress((void**)&p_wcu1,g_wcu1);
    cudaGetSymbolAddress((void**)&p_wp0, g_wp0);  cudaGetSymbolAddress((void**)&p_wp1, g_wp1);

    static bool attr_set = false;
    if (!attr_set) {
        cudaFuncSetAttribute(bgemm_kernel<0>, cudaFuncAttributeMaxDynamicSharedMemorySize, TGE_SMEM);
        cudaFuncSetAttribute(bgemm_kernel<1>, cudaFuncAttributeMaxDynamicSharedMemorySize, TGE_SMEM);
        cudaFuncSetAttribute(bgemm_kernel<2>, cudaFuncAttributeMaxDynamicSharedMemorySize, TGE_SMEM);
        attr_set = true;
    }

    // split weights (transpose to [N][K] bf16 pairs) + layernorm/input splits
    wsplit_kernel<<<TP, 256>>>(W_qkv, W_sem_down, W_ctx_down, W_sem_up, W_ctx_up, W_proj);
    ln_kernel<<<NROWS, 256>>>(x, gamma, beta);

    // qkv = xn @ W_qkv + b_qkv          (4096 x 2304 x 768)
    bgemm_kernel<1><<<dim3(3*DD/128, NROWS/128, 1), 256, TGE_SMEM>>>(
        p_xn0, p_xn1, p_wq0, p_wq1, b_qkv, p_qkv, nullptr, nullptr, 3*DD, DD,
        nullptr, nullptr, nullptr, nullptr, nullptr, nullptr, nullptr);
    // fused down-projections (silu, split out): z=0 sem, z=1 ctx   (4096 x 128 x 768)
    bgemm_kernel<2><<<dim3(RR/128, NROWS/128, 2), 256, TGE_SMEM>>>(
        p_x0, p_x1, p_wsd0, p_wsd1, nullptr, nullptr, p_hs0, p_hs1, RR, DD,
        nullptr, nullptr, p_wcd0, p_wcd1, nullptr, p_hc0, p_hc1);
    // fused up-projections: z=0 sem, z=1 ctx            (4096 x 1536 x 128)
    bgemm_kernel<0><<<dim3(2*DD/128, NROWS/128, 2), 256, TGE_SMEM>>>(
        p_hs0, p_hs1, p_wsu0, p_wsu1, nullptr, p_sem, nullptr, nullptr, 2*DD, RR,
        p_hc0, p_hc1, p_wcu0, p_wcu1, p_ctx, nullptr, nullptr);

    gate_kernel<<<(NROWS*DD)/256, 256>>>(temperature, gate_out);

    chunksum_kernel<<<dim3(NC, BHN), 256>>>();
    scan_kernel<<<BHN, 256>>>();
    attn_kernel<<<dim3(NC, BHN), 256>>>();

    // y = attn @ W_proj + b_proj        (4096 x 768 x 768)
    bgemm_kernel<1><<<dim3(DD/128, NROWS/128, 1), 256, TGE_SMEM>>>(
        p_at0, p_at1, p_wp0, p_wp1, b_proj, y_out, nullptr, nullptr, DD, DD,
        nullptr, nullptr, nullptr, nullptr, nullptr, nullptr, nullptr);
}

// round 7
// speedup vs baseline: 3.4681x; 1.0514x over previous
#include <cuda_runtime.h>
#include <cuda_bf16.h>
#include <math.h>
#include <stdint.h>

#define BB 2
#define LL 2048
#define DD 768
#define HH 12
#define RR 128
#define DH 64
#define NROWS (BB*LL)        // 4096
#define NC 32
#define CT 64
#define BHN (BB*HH)
#define PI_F 3.14159265358979323846f

typedef __nv_bfloat16 bf16;

// ---------------- scratch ---------------------------------------------------
__device__ float g_qkv[NROWS*3*DD];
__device__ float g_sem[NROWS*2*DD];
__device__ float g_ctx[NROWS*2*DD];
__device__ float g_qf[NROWS*DD];
__device__ float g_kf[NROWS*DD];
__device__ float g_vf[NROWS*DD];
__device__ float g_S[BHN*NC*DH*DH];
__device__ float g_z[BHN*NC*DH];

// bf16 split pairs
__device__ bf16 g_xn0[NROWS*DD], g_xn1[NROWS*DD];
__device__ bf16 g_x0[NROWS*DD],  g_x1[NROWS*DD];
__device__ bf16 g_hs0[NROWS*RR], g_hs1[NROWS*RR];
__device__ bf16 g_hc0[NROWS*RR], g_hc1[NROWS*RR];
__device__ bf16 g_at0[NROWS*DD], g_at1[NROWS*DD];
// weights, split + transposed to [N][K]
__device__ bf16 g_wq0[3*DD*DD],  g_wq1[3*DD*DD];
__device__ bf16 g_wsd0[RR*DD],   g_wsd1[RR*DD];
__device__ bf16 g_wcd0[RR*DD],   g_wcd1[RR*DD];
__device__ bf16 g_wsu0[2*DD*RR], g_wsu1[2*DD*RR];
__device__ bf16 g_wcu0[2*DD*RR], g_wcu1[2*DD*RR];
__device__ bf16 g_wp0[DD*DD],    g_wp1[DD*DD];

// ---------------- helpers ----------------------------------------------------
__device__ __forceinline__ uint32_t smem_u32p(const void* p) {
    uint32_t a;
    asm("{ .reg .u64 t; cvta.to.shared.u64 t, %1; cvt.u32.u64 %0, t; }" : "=r"(a) : "l"(p));
    return a;
}
__device__ __forceinline__ void mma_bf16(float* c, const uint32_t* a,
                                         uint32_t b0, uint32_t b1) {
    asm volatile(
        "mma.sync.aligned.m16n8k16.row.col.f32.bf16.bf16.f32 "
        "{%0,%1,%2,%3}, {%4,%5,%6,%7}, {%8,%9}, {%0,%1,%2,%3};"
        : "+f"(c[0]), "+f"(c[1]), "+f"(c[2]), "+f"(c[3])
        : "r"(a[0]), "r"(a[1]), "r"(a[2]), "r"(a[3]), "r"(b0), "r"(b1));
}
__device__ __forceinline__ void cp16(uint32_t sp, const void* gp) {
    asm volatile("cp.async.cg.shared.global [%0], [%1], 16;" :: "r"(sp), "l"(gp) : "memory");
}
__device__ __forceinline__ void split2(float v, bf16& h, bf16& l) {
    h = __float2bfloat16(v);
    l = __float2bfloat16(v - __bfloat162float(h));
}

// ---------------- split-bf16 GEMM (3-term, m16n8k16) -------------------------
// C[M,N] = (A0+A1)[M,K] @ (B0+B1)^T[N,K].  CTA 128xTN, BK=32, 256 thr.
// EPI: 0=plain fp32 out, 1=bias fp32 out, 2=silu + split bf16 pair out
#define ST32 20

template<int EPI, int TN>
__global__ void __launch_bounds__(256, 2) bgemm_kernel(
    const bf16* __restrict__ A0, const bf16* __restrict__ A1,
    const bf16* __restrict__ B0, const bf16* __restrict__ B1,
    const float* __restrict__ bias, float* __restrict__ Cf,
    bf16* __restrict__ C0, bf16* __restrict__ C1,
    int N, int K,
    const bf16* A0b, const bf16* A1b, const bf16* B0b, const bf16* B1b,
    float* Cfb, bf16* C0b, bf16* C1b) {
    constexpr int NT = TN / 16;                      // n-tiles per warp
    constexpr int STAGE_U32 = (256 + 2 * TN) * ST32;
    if (blockIdx.z == 1) {
        if (A0b) { A0 = A0b; A1 = A1b; }
        B0 = B0b; B1 = B1b; Cf = Cfb; C0 = C0b; C1 = C1b;
    }
    extern __shared__ uint32_t smu[];
    uint32_t sbase = smem_u32p(smu);
    int tid = threadIdx.x;
    int lane = tid & 31, wid = tid >> 5;
    int wm = wid & 3, wn = wid >> 2;
    int g = lane >> 2, t4 = lane & 3;
    int m0 = blockIdx.y * 128, n0 = blockIdx.x * TN;

    float c[2][NT][4];
    #pragma unroll
    for (int mt = 0; mt < 2; mt++)
        #pragma unroll
        for (int nt = 0; nt < NT; nt++)
            #pragma unroll
            for (int r = 0; r < 4; r++) c[mt][nt][r] = 0.0f;

    int nstages = K >> 5;

    auto issue = [&](int s, int buf) {
        int k0 = s << 5;
        uint32_t so = sbase + buf * (STAGE_U32 * 4);
        #pragma unroll
        for (int i = 0; i < 2; i++) {
            int ch = tid + i * 256;
            int row = ch >> 2, q = ch & 3;
            uint32_t d = so + (row * ST32 + q * 4) * 4;
            cp16(d,                 A0 + (size_t)(m0 + row) * K + k0 + q * 8);
            cp16(d + 128*ST32*4,    A1 + (size_t)(m0 + row) * K + k0 + q * 8);
        }
        #pragma unroll
        for (int i = 0; i < TN/64; i++) {
            int ch = tid + i * 256;
            int row = ch >> 2, q = ch & 3;
            uint32_t d = so + ((256 + row) * ST32 + q * 4) * 4;
            cp16(d,               B0 + (size_t)(n0 + row) * K + k0 + q * 8);
            cp16(d + TN*ST32*4,   B1 + (size_t)(n0 + row) * K + k0 + q * 8);
        }
        asm volatile("cp.async.commit_group;" ::: "memory");
    };

    issue(0, 0);
    for (int s = 0; s < nstages; s++) {
        int buf = s & 1;
        if (s + 1 < nstages) {
            issue(s + 1, buf ^ 1);
            asm volatile("cp.async.wait_group 1;" ::: "memory");
        } else {
            asm volatile("cp.async.wait_group 0;" ::: "memory");
        }
        __syncthreads();

        const uint32_t* sA0 = smu + buf * STAGE_U32;
        const uint32_t* sA1 = sA0 + 128 * ST32;
        const uint32_t* sB0 = smu + buf * STAGE_U32 + 256 * ST32;
        const uint32_t* sB1 = sB0 + TN * ST32;

        #pragma unroll
        for (int ks = 0; ks < 2; ks++) {
            int kb = ks * 8;
            uint32_t a0f[2][4], a1f[2][4];
            #pragma unroll
            for (int mt = 0; mt < 2; mt++) {
                int r = wm * 32 + mt * 16 + g;
                a0f[mt][0] = sA0[r * ST32 + kb + t4];
                a0f[mt][1] = sA0[(r + 8) * ST32 + kb + t4];
                a0f[mt][2] = sA0[r * ST32 + kb + t4 + 4];
                a0f[mt][3] = sA0[(r + 8) * ST32 + kb + t4 + 4];
                a1f[mt][0] = sA1[r * ST32 + kb + t4];
                a1f[mt][1] = sA1[(r + 8) * ST32 + kb + t4];
                a1f[mt][2] = sA1[r * ST32 + kb + t4 + 4];
                a1f[mt][3] = sA1[(r + 8) * ST32 + kb + t4 + 4];
            }
            #pragma unroll
            for (int nt = 0; nt < NT; nt++) {
                int n = wn * (TN/2) + nt * 8 + g;
                uint32_t b00 = sB0[n * ST32 + kb + t4];
                uint32_t b01 = sB0[n * ST32 + kb + t4 + 4];
                uint32_t b10 = sB1[n * ST32 + kb + t4];
                uint32_t b11 = sB1[n * ST32 + kb + t4 + 4];
                #pragma unroll
                for (int mt = 0; mt < 2; mt++) {
                    mma_bf16(c[mt][nt], a0f[mt], b00, b01);
                    mma_bf16(c[mt][nt], a0f[mt], b10, b11);
                    mma_bf16(c[mt][nt], a1f[mt], b00, b01);
                }
            }
        }
        __syncthreads();
    }

    // ---- epilogue ----
    #pragma unroll
    for (int mt = 0; mt < 2; mt++) {
        int row = m0 + wm * 32 + mt * 16 + g;
        #pragma unroll
        for (int nt = 0; nt < NT; nt++) {
            int col = n0 + wn * (TN/2) + nt * 8 + 2 * t4;
            float v0 = c[mt][nt][0], v1 = c[mt][nt][1];
            float v2 = c[mt][nt][2], v3 = c[mt][nt][3];
            if (EPI == 1) {
                float b0 = bias[col], b1 = bias[col + 1];
                v0 += b0; v1 += b1; v2 += b0; v3 += b1;
            }
            if (EPI == 2) {
                v0 = v0 * __fdividef(1.0f, 1.0f + __expf(-v0));
                v1 = v1 * __fdividef(1.0f, 1.0f + __expf(-v1));
                v2 = v2 * __fdividef(1.0f, 1.0f + __expf(-v2));
                v3 = v3 * __fdividef(1.0f, 1.0f + __expf(-v3));
                bf16 h0, l0, h1, l1, h2, l2, h3, l3;
                split2(v0, h0, l0); split2(v1, h1, l1);
                split2(v2, h2, l2); split2(v3, h3, l3);
                __nv_bfloat162 ph0; ph0.x = h0; ph0.y = h1;
                __nv_bfloat162 pl0; pl0.x = l0; pl0.y = l1;
                __nv_bfloat162 ph1; ph1.x = h2; ph1.y = h3;
                __nv_bfloat162 pl1; pl1.x = l2; pl1.y = l3;
                *(__nv_bfloat162*)(C0 + (size_t)row * N + col)       = ph0;
                *(__nv_bfloat162*)(C1 + (size_t)row * N + col)       = pl0;
                *(__nv_bfloat162*)(C0 + (size_t)(row + 8) * N + col) = ph1;
                *(__nv_bfloat162*)(C1 + (size_t)(row + 8) * N + col) = pl1;
            } else {
                *(float2*)(Cf + (size_t)row * N + col)       = make_float2(v0, v1);
                *(float2*)(Cf + (size_t)(row + 8) * N + col) = make_float2(v2, v3);
            }
        }
    }
}

// ---------------- weight split + transpose -----------------------------------
#define TQ  1728
#define TSD (TQ + 96)
#define TCD (TSD + 96)
#define TSU (TCD + 192)
#define TCU (TSU + 192)
#define TP  (TCU + 576)
__global__ void wsplit_kernel(
    const float* __restrict__ Wq, const float* __restrict__ Wsd,
    const float* __restrict__ Wcd, const float* __restrict__ Wsu,
    const float* __restrict__ Wcu, const float* __restrict__ Wp) {
    int t = blockIdx.x;
    const float* W; bf16 *D0, *D1; int K, N;
    if (t < TQ)       { W = Wq;  D0 = g_wq0;  D1 = g_wq1;  K = DD;  N = 3*DD; }
    else if (t < TSD) { t -= TQ;  W = Wsd; D0 = g_wsd0; D1 = g_wsd1; K = DD;  N = RR; }
    else if (t < TCD) { t -= TSD; W = Wcd; D0 = g_wcd0; D1 = g_wcd1; K = DD;  N = RR; }
    else if (t < TSU) { t -= TCD; W = Wsu; D0 = g_wsu0; D1 = g_wsu1; K = RR;  N = 2*DD; }
    else if (t < TCU) { t -= TSU; W = Wcu; D0 = g_wcu0; D1 = g_wcu1; K = RR;  N = 2*DD; }
    else              { t -= TCU; W = Wp;  D0 = g_wp0;  D1 = g_wp1;  K = DD;  N = DD; }
    int tN = N >> 5;
    int k0 = (t / tN) << 5, n0 = (t % tN) << 5;
    __shared__ float sm[32][33];
    int tx = threadIdx.x & 31, ty = threadIdx.x >> 5;
    #pragma unroll
    for (int i = 0; i < 4; i++)
        sm[ty + 8*i][tx] = W[(size_t)(k0 + ty + 8*i) * N + n0 + tx];
    __syncthreads();
    #pragma unroll
    for (int i = 0; i < 4; i++) {
        float v = sm[tx][ty + 8*i];
        bf16 h, l; split2(v, h, l);
        size_t o = (size_t)(n0 + ty + 8*i) * K + k0 + tx;
        D0[o] = h; D1[o] = l;
    }
}

// ---------------- layernorm + input splits -----------------------------------
__global__ void ln_kernel(const float* __restrict__ x,
                          const float* __restrict__ gamma,
                          const float* __restrict__ beta) {
    int row = blockIdx.x;
    const float* xr = x + (size_t)row*DD;
    int t = threadIdx.x;
    float v0 = xr[t], v1 = xr[t+256], v2 = xr[t+512];
    __shared__ float red[256], red2[256];
    red[t]  = v0+v1+v2;
    red2[t] = v0*v0+v1*v1+v2*v2;
    __syncthreads();
    for (int o = 128; o > 0; o >>= 1) {
        if (t < o) { red[t] += red[t+o]; red2[t] += red2[t+o]; }
        __syncthreads();
    }
    float mu  = red[0] * (1.0f/DD);
    float var = red2[0] * (1.0f/DD) - mu*mu;
    float inv = rsqrtf(var + 1e-5f);
    size_t base = (size_t)row*DD;
    float vv[3] = {v0, v1, v2};
    #pragma unroll
    for (int i = 0; i < 3; i++) {
        int d = t + i*256;
        float xn = (vv[i]-mu)*inv*gamma[d] + beta[d];
        bf16 h, l;
        split2(xn, h, l);    g_xn0[base+d] = h; g_xn1[base+d] = l;
        split2(vv[i], h, l); g_x0[base+d]  = h; g_x1[base+d]  = l;
    }
}

// ---------------- gate (fast transcendentals) --------------------------------
__device__ __forceinline__ float softplus_f(float a) {
    return a > 15.0f ? a : __logf(1.0f + __expf(a));
}
__device__ __forceinline__ float tanh_f(float a) {
    float x = fminf(fmaxf(a, -15.0f), 15.0f);
    float t = __expf(2.0f * x);
    return __fdividef(t - 1.0f, t + 1.0f);
}
__global__ void gate_kernel(const float* __restrict__ temperature,
                            float* __restrict__ gate_out) {
    int idx = blockIdx.x*256 + threadIdx.x;
    int row = idx / DD, d = idx - row*DD;
    const float* sr = g_sem + (size_t)row*(2*DD);
    const float* cr = g_ctx + (size_t)row*(2*DD);
    float sa = softplus_f(sr[d]);
    float sp = tanh_f(sr[DD + d]) * PI_F;
    float ca = softplus_f(cr[d]);
    float cp = tanh_f(cr[DD + d]) * PI_F;
    float inter = sa * ca * __cosf(sp - cp) * temperature[0];
    float gate = __fdividef(1.0f, 1.0f + __expf(-inter));
    gate_out[idx] = gate;

    const float* qr = g_qkv + (size_t)row*(3*DD);
    float q = qr[d];
    float k = qr[DD + d] * (1.0f + gate);
    float v = qr[2*DD + d];
    float qfv = q > 0.0f ? q + 1.0f : __expf(q);
    float kfv = k > 0.0f ? k + 1.0f : __expf(k);
    int b = row / LL, l = row - b*LL;
    int h = d / DH, dh = d - h*DH;
    int hid = ((b*HH + h)*LL + l)*DH + dh;
    g_qf[hid] = qfv;
    g_kf[hid] = kfv;
    g_vf[hid] = v;
}

// ---------------- chunked linear attention ------------------------------------
__global__ void chunksum_kernel() {
    int c  = blockIdx.x;
    int bh = blockIdx.y;
    __shared__ float ks[CT][DH];
    __shared__ float vs[CT][DH];
    int tid = threadIdx.x;
    int base = (bh*LL + c*CT)*DH;
    for (int i = tid; i < CT*DH; i += 256) {
        ks[i/DH][i%DH] = g_kf[base + i];
        vs[i/DH][i%DH] = g_vf[base + i];
    }
    __syncthreads();
    int d  = tid >> 2;
    int e0 = (tid & 3) * 16;
    float acc[16] = {};
    float zacc = 0.0f;
    for (int l = 0; l < CT; l++) {
        float kd = ks[l][d];
        zacc += kd;
        #pragma unroll
        for (int u = 0; u < 16; u++) acc[u] += kd * vs[l][e0 + u];
    }
    float* Sp = g_S + (size_t)(bh*NC + c)*DH*DH;
    #pragma unroll
    for (int u = 0; u < 16; u++) Sp[d*DH + e0 + u] = acc[u];
    if ((tid & 3) == 0) g_z[(bh*NC + c)*DH + d] = zacc;
}

__global__ void scan_kernel() {
    int bh = blockIdx.x;
    int e = blockIdx.y * 256 + threadIdx.x;
    float* p = g_S + (size_t)bh*NC*DH*DH + e;
    float run = 0.0f;
    #pragma unroll
    for (int c = 0; c < NC; c++) {
        float t = p[(size_t)c*DH*DH];
        p[(size_t)c*DH*DH] = run;
        run += t;
    }
    if (blockIdx.y == 0 && threadIdx.x < DH) {
        float* pz = g_z + bh*NC*DH + threadIdx.x;
        float rz = 0.0f;
        #pragma unroll
        for (int c = 0; c < NC; c++) {
            float t = pz[c*DH];
            pz[c*DH] = rz;
            rz += t;
        }
    }
}

__global__ void attn_kernel() {
    int c  = blockIdx.x;
    int bh = blockIdx.y;
    __shared__ float qs[CT][DH+1];
    __shared__ float ks[CT][DH+1];
    int tid = threadIdx.x;
    int base = (bh*LL + c*CT)*DH;
    for (int i = tid; i < CT*DH; i += 256) {
        qs[i/DH][i%DH] = g_qf[base + i];
        ks[i/DH][i%DH] = g_kf[base + i];
    }
    __syncthreads();
    int i  = tid >> 2;
    int e0 = (tid & 3) * 16;
    const float* Sp = g_S + (size_t)(bh*NC + c)*DH*DH;
    const float* zp = g_z + (bh*NC + c)*DH;
    const float* vg = g_vf + base;

    float acc[16] = {};
    float den = 1e-6f;
    for (int d = 0; d < DH; d++) {
        float qd = qs[i][d];
        den += qd * zp[d];
        const float* sr = Sp + d*DH + e0;
        #pragma unroll
        for (int u = 0; u < 16; u++) acc[u] += qd * sr[u];
    }
    for (int j = 0; j <= i; j++) {
        float s = 0.0f;
        #pragma unroll
        for (int d = 0; d < DH; d++) s += qs[i][d] * ks[j][d];
        den += s;
        const float* vr = vg + j*DH + e0;
        #pragma unroll
        for (int u = 0; u < 16; u++) acc[u] += s * vr[u];
    }
    int b = bh / HH, h = bh - b*HH;
    int l = c*CT + i;
    size_t obase = (size_t)(b*LL + l)*DD + h*DH + e0;
    float invd = __fdividef(1.0f, den);
    #pragma unroll
    for (int u = 0; u < 16; u += 2) {
        float o0 = acc[u] * invd, o1 = acc[u+1] * invd;
        bf16 h0, l0, h1, l1;
        split2(o0, h0, l0); split2(o1, h1, l1);
        __nv_bfloat162 ph; ph.x = h0; ph.y = h1;
        __nv_bfloat162 pl; pl.x = l0; pl.y = l1;
        *(__nv_bfloat162*)(g_at0 + obase + u) = ph;
        *(__nv_bfloat162*)(g_at1 + obase + u) = pl;
    }
}

// ---------------- launch -------------------------------------------------------
extern "C" void kernel_launch(void* const* d_in, const int* in_sizes, int n_in,
                              void* d_out, int out_size) {
    const float* x          = (const float*)d_in[0];
    const float* W_qkv      = (const float*)d_in[1];
    const float* b_qkv      = (const float*)d_in[2];
    const float* W_sem_down = (const float*)d_in[3];
    const float* W_sem_up   = (const float*)d_in[4];
    const float* W_ctx_down = (const float*)d_in[5];
    const float* W_ctx_up   = (const float*)d_in[6];
    const float* temperature= (const float*)d_in[7];
    const float* W_proj     = (const float*)d_in[8];
    const float* b_proj     = (const float*)d_in[9];
    const float* gamma      = (const float*)d_in[10];
    const float* beta       = (const float*)d_in[11];
    float* y_out    = (float*)d_out;
    float* gate_out = y_out + (size_t)NROWS*DD;

    float *p_qkv, *p_sem, *p_ctx;
    bf16 *p_xn0, *p_xn1, *p_x0, *p_x1, *p_hs0, *p_hs1, *p_hc0, *p_hc1, *p_at0, *p_at1;
    bf16 *p_wq0, *p_wq1, *p_wsd0, *p_wsd1, *p_wcd0, *p_wcd1;
    bf16 *p_wsu0, *p_wsu1, *p_wcu0, *p_wcu1, *p_wp0, *p_wp1;
    cudaGetSymbolAddress((void**)&p_qkv, g_qkv);
    cudaGetSymbolAddress((void**)&p_sem, g_sem);
    cudaGetSymbolAddress((void**)&p_ctx, g_ctx);
    cudaGetSymbolAddress((void**)&p_xn0, g_xn0);  cudaGetSymbolAddress((void**)&p_xn1, g_xn1);
    cudaGetSymbolAddress((void**)&p_x0,  g_x0);   cudaGetSymbolAddress((void**)&p_x1,  g_x1);
    cudaGetSymbolAddress((void**)&p_hs0, g_hs0);  cudaGetSymbolAddress((void**)&p_hs1, g_hs1);
    cudaGetSymbolAddress((void**)&p_hc0, g_hc0);  cudaGetSymbolAddress((void**)&p_hc1, g_hc1);
    cudaGetSymbolAddress((void**)&p_at0, g_at0);  cudaGetSymbolAddress((void**)&p_at1, g_at1);
    cudaGetSymbolAddress((void**)&p_wq0, g_wq0);  cudaGetSymbolAddress((void**)&p_wq1, g_wq1);
    cudaGetSymbolAddress((void**)&p_wsd0,g_wsd0); cudaGetSymbolAddress((void**)&p_wsd1,g_wsd1);
    cudaGetSymbolAddress((void**)&p_wcd0,g_wcd0); cudaGetSymbolAddress((void**)&p_wcd1,g_wcd1);
    cudaGetSymbolAddress((void**)&p_wsu0,g_wsu0); cudaGetSymbolAddress((void**)&p_wsu1,g_wsu1);
    cudaGetSymbolAddress((void**)&p_wcu0,g_wcu0); cudaGetSymbolAddress((void**)&p_wcu1,g_wcu1);
    cudaGetSymbolAddress((void**)&p_wp0, g_wp0);  cudaGetSymbolAddress((void**)&p_wp1, g_wp1);

    constexpr int SMEM128 = 2 * (256 + 256) * ST32 * 4;   // 81920
    constexpr int SMEM64  = 2 * (256 + 128) * ST32 * 4;   // 61440

    static bool attr_set = false;
    if (!attr_set) {
        cudaFuncSetAttribute((const void*)bgemm_kernel<0,128>, cudaFuncAttributeMaxDynamicSharedMemorySize, SMEM128);
        cudaFuncSetAttribute((const void*)bgemm_kernel<1,128>, cudaFuncAttributeMaxDynamicSharedMemorySize, SMEM128);
        cudaFuncSetAttribute((const void*)bgemm_kernel<2,64>,  cudaFuncAttributeMaxDynamicSharedMemorySize, SMEM64);
        attr_set = true;
    }

    wsplit_kernel<<<TP, 256>>>(W_qkv, W_sem_down, W_ctx_down, W_sem_up, W_ctx_up, W_proj);
    ln_kernel<<<NROWS, 256>>>(x, gamma, beta);

    // qkv = xn @ W_qkv + b_qkv          (4096 x 2304 x 768)
    bgemm_kernel<1,128><<<dim3(3*DD/128, NROWS/128, 1), 256, SMEM128>>>(
        p_xn0, p_xn1, p_wq0, p_wq1, b_qkv, p_qkv, nullptr, nullptr, 3*DD, DD,
        nullptr, nullptr, nullptr, nullptr, nullptr, nullptr, nullptr);
    // fused down-projections (silu, split out, TN=64): z=0 sem, z=1 ctx
    bgemm_kernel<2,64><<<dim3(RR/64, NROWS/128, 2), 256, SMEM64>>>(
        p_x0, p_x1, p_wsd0, p_wsd1, nullptr, nullptr, p_hs0, p_hs1, RR, DD,
        nullptr, nullptr, p_wcd0, p_wcd1, nullptr, p_hc0, p_hc1);
    // fused up-projections: z=0 sem, z=1 ctx            (4096 x 1536 x 128)
    bgemm_kernel<0,128><<<dim3(2*DD/128, NROWS/128, 2), 256, SMEM128>>>(
        p_hs0, p_hs1, p_wsu0, p_wsu1, nullptr, p_sem, nullptr, nullptr, 2*DD, RR,
        p_hc0, p_hc1, p_wcu0, p_wcu1, p_ctx, nullptr, nullptr);

    gate_kernel<<<(NROWS*DD)/256, 256>>>(temperature, gate_out);

    chunksum_kernel<<<dim3(NC, BHN), 256>>>();
    scan_kernel<<<dim3(BHN, 16), 256>>>();
    attn_kernel<<<dim3(NC, BHN), 256>>>();

    // y = attn @ W_proj + b_proj        (4096 x 768 x 768)
    bgemm_kernel<1,128><<<dim3(DD/128, NROWS/128, 1), 256, SMEM128>>>(
        p_at0, p_at1, p_wp0, p_wp1, b_proj, y_out, nullptr, nullptr, DD, DD,
        nullptr, nullptr, nullptr, nullptr, nullptr, nullptr, nullptr);
}

// round 8
// speedup vs baseline: 4.8827x; 1.4079x over previous
#include <cuda_runtime.h>
#include <cuda_bf16.h>
#include <math.h>
#include <stdint.h>

#define BB 2
#define LL 2048
#define DD 768
#define HH 12
#define RR 128
#define DH 64
#define NROWS (BB*LL)        // 4096
#define NC 32
#define CT 64
#define BHN (BB*HH)
#define PI_F 3.14159265358979323846f

typedef __nv_bfloat16 bf16;

// ---------------- scratch ---------------------------------------------------
__device__ float g_qkv[NROWS*3*DD];
__device__ float g_sem[NROWS*2*DD];
__device__ float g_ctx[NROWS*2*DD];
__device__ float g_qf[NROWS*DD];
__device__ float g_kf[NROWS*DD];
__device__ float g_vf[NROWS*DD];
__device__ float g_S[BHN*NC*DH*DH];
__device__ float g_z[BHN*NC*DH];

// bf16 split pairs
__device__ bf16 g_xn0[NROWS*DD], g_xn1[NROWS*DD];
__device__ bf16 g_x0[NROWS*DD],  g_x1[NROWS*DD];
__device__ bf16 g_hs0[NROWS*RR], g_hs1[NROWS*RR];
__device__ bf16 g_hc0[NROWS*RR], g_hc1[NROWS*RR];
__device__ bf16 g_at0[NROWS*DD], g_at1[NROWS*DD];
// weights, split + transposed to [N][K]
__device__ bf16 g_wq0[3*DD*DD],  g_wq1[3*DD*DD];
__device__ bf16 g_wsd0[RR*DD],   g_wsd1[RR*DD];
__device__ bf16 g_wcd0[RR*DD],   g_wcd1[RR*DD];
__device__ bf16 g_wsu0[2*DD*RR], g_wsu1[2*DD*RR];
__device__ bf16 g_wcu0[2*DD*RR], g_wcu1[2*DD*RR];
__device__ bf16 g_wp0[DD*DD],    g_wp1[DD*DD];

// ---------------- helpers ----------------------------------------------------
__device__ __forceinline__ uint32_t smem_u32p(const void* p) {
    uint32_t a;
    asm("{ .reg .u64 t; cvta.to.shared.u64 t, %1; cvt.u32.u64 %0, t; }" : "=r"(a) : "l"(p));
    return a;
}
__device__ __forceinline__ void mma_bf16(float* c, const uint32_t* a,
                                         uint32_t b0, uint32_t b1) {
    asm volatile(
        "mma.sync.aligned.m16n8k16.row.col.f32.bf16.bf16.f32 "
        "{%0,%1,%2,%3}, {%4,%5,%6,%7}, {%8,%9}, {%0,%1,%2,%3};"
        : "+f"(c[0]), "+f"(c[1]), "+f"(c[2]), "+f"(c[3])
        : "r"(a[0]), "r"(a[1]), "r"(a[2]), "r"(a[3]), "r"(b0), "r"(b1));
}
__device__ __forceinline__ void cp16(uint32_t sp, const void* gp) {
    asm volatile("cp.async.cg.shared.global [%0], [%1], 16;" :: "r"(sp), "l"(gp) : "memory");
}
__device__ __forceinline__ void split2(float v, bf16& h, bf16& l) {
    h = __float2bfloat16(v);
    l = __float2bfloat16(v - __bfloat162float(h));
}

// ---------------- split-bf16 GEMM (3-term, m16n8k16) -------------------------
#define ST32 20

template<int EPI, int TN>
__global__ void __launch_bounds__(256, 2) bgemm_kernel(
    const bf16* __restrict__ A0, const bf16* __restrict__ A1,
    const bf16* __restrict__ B0, const bf16* __restrict__ B1,
    const float* __restrict__ bias, float* __restrict__ Cf,
    bf16* __restrict__ C0, bf16* __restrict__ C1,
    int N, int K,
    const bf16* A0b, const bf16* A1b, const bf16* B0b, const bf16* B1b,
    float* Cfb, bf16* C0b, bf16* C1b) {
    constexpr int NT = TN / 16;
    constexpr int STAGE_U32 = (256 + 2 * TN) * ST32;
    if (blockIdx.z == 1) {
        if (A0b) { A0 = A0b; A1 = A1b; }
        B0 = B0b; B1 = B1b; Cf = Cfb; C0 = C0b; C1 = C1b;
    }
    extern __shared__ uint32_t smu[];
    uint32_t sbase = smem_u32p(smu);
    int tid = threadIdx.x;
    int lane = tid & 31, wid = tid >> 5;
    int wm = wid & 3, wn = wid >> 2;
    int g = lane >> 2, t4 = lane & 3;
    int m0 = blockIdx.y * 128, n0 = blockIdx.x * TN;

    float c[2][NT][4];
    #pragma unroll
    for (int mt = 0; mt < 2; mt++)
        #pragma unroll
        for (int nt = 0; nt < NT; nt++)
            #pragma unroll
            for (int r = 0; r < 4; r++) c[mt][nt][r] = 0.0f;

    int nstages = K >> 5;

    auto issue = [&](int s, int buf) {
        int k0 = s << 5;
        uint32_t so = sbase + buf * (STAGE_U32 * 4);
        #pragma unroll
        for (int i = 0; i < 2; i++) {
            int ch = tid + i * 256;
            int row = ch >> 2, q = ch & 3;
            uint32_t d = so + (row * ST32 + q * 4) * 4;
            cp16(d,                 A0 + (size_t)(m0 + row) * K + k0 + q * 8);
            cp16(d + 128*ST32*4,    A1 + (size_t)(m0 + row) * K + k0 + q * 8);
        }
        #pragma unroll
        for (int i = 0; i < TN/64; i++) {
            int ch = tid + i * 256;
            int row = ch >> 2, q = ch & 3;
            uint32_t d = so + ((256 + row) * ST32 + q * 4) * 4;
            cp16(d,               B0 + (size_t)(n0 + row) * K + k0 + q * 8);
            cp16(d + TN*ST32*4,   B1 + (size_t)(n0 + row) * K + k0 + q * 8);
        }
        asm volatile("cp.async.commit_group;" ::: "memory");
    };

    issue(0, 0);
    for (int s = 0; s < nstages; s++) {
        int buf = s & 1;
        if (s + 1 < nstages) {
            issue(s + 1, buf ^ 1);
            asm volatile("cp.async.wait_group 1;" ::: "memory");
        } else {
            asm volatile("cp.async.wait_group 0;" ::: "memory");
        }
        __syncthreads();

        const uint32_t* sA0 = smu + buf * STAGE_U32;
        const uint32_t* sA1 = sA0 + 128 * ST32;
        const uint32_t* sB0 = smu + buf * STAGE_U32 + 256 * ST32;
        const uint32_t* sB1 = sB0 + TN * ST32;

        #pragma unroll
        for (int ks = 0; ks < 2; ks++) {
            int kb = ks * 8;
            uint32_t a0f[2][4], a1f[2][4];
            #pragma unroll
            for (int mt = 0; mt < 2; mt++) {
                int r = wm * 32 + mt * 16 + g;
                a0f[mt][0] = sA0[r * ST32 + kb + t4];
                a0f[mt][1] = sA0[(r + 8) * ST32 + kb + t4];
                a0f[mt][2] = sA0[r * ST32 + kb + t4 + 4];
                a0f[mt][3] = sA0[(r + 8) * ST32 + kb + t4 + 4];
                a1f[mt][0] = sA1[r * ST32 + kb + t4];
                a1f[mt][1] = sA1[(r + 8) * ST32 + kb + t4];
                a1f[mt][2] = sA1[r * ST32 + kb + t4 + 4];
                a1f[mt][3] = sA1[(r + 8) * ST32 + kb + t4 + 4];
            }
            #pragma unroll
            for (int nt = 0; nt < NT; nt++) {
                int n = wn * (TN/2) + nt * 8 + g;
                uint32_t b00 = sB0[n * ST32 + kb + t4];
                uint32_t b01 = sB0[n * ST32 + kb + t4 + 4];
                uint32_t b10 = sB1[n * ST32 + kb + t4];
                uint32_t b11 = sB1[n * ST32 + kb + t4 + 4];
                #pragma unroll
                for (int mt = 0; mt < 2; mt++) {
                    mma_bf16(c[mt][nt], a0f[mt], b00, b01);
                    mma_bf16(c[mt][nt], a0f[mt], b10, b11);
                    mma_bf16(c[mt][nt], a1f[mt], b00, b01);
                }
            }
        }
        __syncthreads();
    }

    #pragma unroll
    for (int mt = 0; mt < 2; mt++) {
        int row = m0 + wm * 32 + mt * 16 + g;
        #pragma unroll
        for (int nt = 0; nt < NT; nt++) {
            int col = n0 + wn * (TN/2) + nt * 8 + 2 * t4;
            float v0 = c[mt][nt][0], v1 = c[mt][nt][1];
            float v2 = c[mt][nt][2], v3 = c[mt][nt][3];
            if (EPI == 1) {
                float b0 = bias[col], b1 = bias[col + 1];
                v0 += b0; v1 += b1; v2 += b0; v3 += b1;
            }
            if (EPI == 2) {
                v0 = v0 * __fdividef(1.0f, 1.0f + __expf(-v0));
                v1 = v1 * __fdividef(1.0f, 1.0f + __expf(-v1));
                v2 = v2 * __fdividef(1.0f, 1.0f + __expf(-v2));
                v3 = v3 * __fdividef(1.0f, 1.0f + __expf(-v3));
                bf16 h0, l0, h1, l1, h2, l2, h3, l3;
                split2(v0, h0, l0); split2(v1, h1, l1);
                split2(v2, h2, l2); split2(v3, h3, l3);
                __nv_bfloat162 ph0; ph0.x = h0; ph0.y = h1;
                __nv_bfloat162 pl0; pl0.x = l0; pl0.y = l1;
                __nv_bfloat162 ph1; ph1.x = h2; ph1.y = h3;
                __nv_bfloat162 pl1; pl1.x = l2; pl1.y = l3;
                *(__nv_bfloat162*)(C0 + (size_t)row * N + col)       = ph0;
                *(__nv_bfloat162*)(C1 + (size_t)row * N + col)       = pl0;
                *(__nv_bfloat162*)(C0 + (size_t)(row + 8) * N + col) = ph1;
                *(__nv_bfloat162*)(C1 + (size_t)(row + 8) * N + col) = pl1;
            } else {
                *(float2*)(Cf + (size_t)row * N + col)       = make_float2(v0, v1);
                *(float2*)(Cf + (size_t)(row + 8) * N + col) = make_float2(v2, v3);
            }
        }
    }
}

// ---------------- prep: weight split + layernorm (merged) --------------------
#define TQ  1728
#define TSD (TQ + 96)
#define TCD (TSD + 96)
#define TSU (TCD + 192)
#define TCU (TSU + 192)
#define TP  (TCU + 576)
__global__ void prep_kernel(
    const float* __restrict__ Wq, const float* __restrict__ Wsd,
    const float* __restrict__ Wcd, const float* __restrict__ Wsu,
    const float* __restrict__ Wcu, const float* __restrict__ Wp,
    const float* __restrict__ x, const float* __restrict__ gamma,
    const float* __restrict__ beta) {
    int bid = blockIdx.x;
    if (bid < TP) {
        int t = bid;
        const float* W; bf16 *D0, *D1; int K, N;
        if (t < TQ)       { W = Wq;  D0 = g_wq0;  D1 = g_wq1;  K = DD;  N = 3*DD; }
        else if (t < TSD) { t -= TQ;  W = Wsd; D0 = g_wsd0; D1 = g_wsd1; K = DD;  N = RR; }
        else if (t < TCD) { t -= TSD; W = Wcd; D0 = g_wcd0; D1 = g_wcd1; K = DD;  N = RR; }
        else if (t < TSU) { t -= TCD; W = Wsu; D0 = g_wsu0; D1 = g_wsu1; K = RR;  N = 2*DD; }
        else if (t < TCU) { t -= TSU; W = Wcu; D0 = g_wcu0; D1 = g_wcu1; K = RR;  N = 2*DD; }
        else              { t -= TCU; W = Wp;  D0 = g_wp0;  D1 = g_wp1;  K = DD;  N = DD; }
        int tN = N >> 5;
        int k0 = (t / tN) << 5, n0 = (t % tN) << 5;
        __shared__ float sm[32][33];
        int tx = threadIdx.x & 31, ty = threadIdx.x >> 5;
        #pragma unroll
        for (int i = 0; i < 4; i++)
            sm[ty + 8*i][tx] = W[(size_t)(k0 + ty + 8*i) * N + n0 + tx];
        __syncthreads();
        #pragma unroll
        for (int i = 0; i < 4; i++) {
            float v = sm[tx][ty + 8*i];
            bf16 h, l; split2(v, h, l);
            size_t o = (size_t)(n0 + ty + 8*i) * K + k0 + tx;
            D0[o] = h; D1[o] = l;
        }
    } else {
        int row = bid - TP;
        const float* xr = x + (size_t)row*DD;
        int t = threadIdx.x;
        float v0 = xr[t], v1 = xr[t+256], v2 = xr[t+512];
        __shared__ float red[256], red2[256];
        red[t]  = v0+v1+v2;
        red2[t] = v0*v0+v1*v1+v2*v2;
        __syncthreads();
        for (int o = 128; o > 0; o >>= 1) {
            if (t < o) { red[t] += red[t+o]; red2[t] += red2[t+o]; }
            __syncthreads();
        }
        float mu  = red[0] * (1.0f/DD);
        float var = red2[0] * (1.0f/DD) - mu*mu;
        float inv = rsqrtf(var + 1e-5f);
        size_t base = (size_t)row*DD;
        float vv[3] = {v0, v1, v2};
        #pragma unroll
        for (int i = 0; i < 3; i++) {
            int d = t + i*256;
            float xn = (vv[i]-mu)*inv*gamma[d] + beta[d];
            bf16 h, l;
            split2(xn, h, l);    g_xn0[base+d] = h; g_xn1[base+d] = l;
            split2(vv[i], h, l); g_x0[base+d]  = h; g_x1[base+d]  = l;
        }
    }
}

// ---------------- gate (fast transcendentals) --------------------------------
__device__ __forceinline__ float softplus_f(float a) {
    return a > 15.0f ? a : __logf(1.0f + __expf(a));
}
__device__ __forceinline__ float tanh_f(float a) {
    float x = fminf(fmaxf(a, -15.0f), 15.0f);
    float t = __expf(2.0f * x);
    return __fdividef(t - 1.0f, t + 1.0f);
}
__global__ void gate_kernel(const float* __restrict__ temperature,
                            float* __restrict__ gate_out) {
    int idx = blockIdx.x*256 + threadIdx.x;
    int row = idx / DD, d = idx - row*DD;
    const float* sr = g_sem + (size_t)row*(2*DD);
    const float* cr = g_ctx + (size_t)row*(2*DD);
    float sa = softplus_f(sr[d]);
    float sp = tanh_f(sr[DD + d]) * PI_F;
    float ca = softplus_f(cr[d]);
    float cp = tanh_f(cr[DD + d]) * PI_F;
    float inter = sa * ca * __cosf(sp - cp) * temperature[0];
    float gate = __fdividef(1.0f, 1.0f + __expf(-inter));
    gate_out[idx] = gate;

    const float* qr = g_qkv + (size_t)row*(3*DD);
    float q = qr[d];
    float k = qr[DD + d] * (1.0f + gate);
    float v = qr[2*DD + d];
    float qfv = q > 0.0f ? q + 1.0f : __expf(q);
    float kfv = k > 0.0f ? k + 1.0f : __expf(k);
    int b = row / LL, l = row - b*LL;
    int h = d / DH, dh = d - h*DH;
    int hid = ((b*HH + h)*LL + l)*DH + dh;
    g_qf[hid] = qfv;
    g_kf[hid] = kfv;
    g_vf[hid] = v;
}

// ---------------- chunked linear attention ------------------------------------
__global__ void chunksum_kernel() {
    int c  = blockIdx.x;
    int bh = blockIdx.y;
    __shared__ float  ksm[CT][DH+1];
    __shared__ float4 vsm[CT][16];
    int tid = threadIdx.x;
    int base = (bh*LL + c*CT)*DH;
    for (int idx = tid; idx < CT*16; idx += 256) {
        int row = idx >> 4, kk = idx & 15;
        float4 kv = ((const float4*)(g_kf + base))[idx];
        ksm[row][kk*4+0] = kv.x; ksm[row][kk*4+1] = kv.y;
        ksm[row][kk*4+2] = kv.z; ksm[row][kk*4+3] = kv.w;
        vsm[row][kk] = ((const float4*)(g_vf + base))[idx];
    }
    __syncthreads();
    int d = tid >> 2, t4 = tid & 3;
    float4 acc[4] = {};
    float zacc = 0.0f;
    for (int l = 0; l < CT; l++) {
        float kd = ksm[l][d];
        zacc += kd;
        #pragma unroll
        for (int r = 0; r < 4; r++) {
            float4 v = vsm[l][t4*4 + r];
            acc[r].x += kd*v.x; acc[r].y += kd*v.y;
            acc[r].z += kd*v.z; acc[r].w += kd*v.w;
        }
    }
    float4* Sp = (float4*)(g_S + (size_t)(bh*NC + c)*DH*DH + d*DH + t4*16);
    #pragma unroll
    for (int r = 0; r < 4; r++) Sp[r] = acc[r];
    if (t4 == 0) g_z[(bh*NC + c)*DH + d] = zacc;
}

__global__ void scan_kernel() {
    int bh = blockIdx.x;
    int e = blockIdx.y * 256 + threadIdx.x;
    float* p = g_S + (size_t)bh*NC*DH*DH + e;
    float run = 0.0f;
    #pragma unroll
    for (int c = 0; c < NC; c++) {
        float t = p[(size_t)c*DH*DH];
        p[(size_t)c*DH*DH] = run;
        run += t;
    }
    if (blockIdx.y == 0 && threadIdx.x < DH) {
        float* pz = g_z + bh*NC*DH + threadIdx.x;
        float rz = 0.0f;
        #pragma unroll
        for (int c = 0; c < NC; c++) {
            float t = pz[c*DH];
            pz[c*DH] = rz;
            rz += t;
        }
    }
}

// attn: phase A scores once into smem, phase B triangular S·V + inter-chunk
#define ATTN_SMEM ((CT*17 + CT*16 + CT*16)*16 + CT*(CT+1)*4 + CT*4)
__global__ void __launch_bounds__(256) attn_kernel() {
    int c  = blockIdx.x;
    int bh = blockIdx.y;
    extern __shared__ char asmem[];
    float4* qsm = (float4*)asmem;            // [CT][17] padded
    float4* ksm = qsm + CT*17;               // [CT][16] xor-swizzled
    float4* vsm = ksm + CT*16;               // [CT][16]
    float*  ss  = (float*)(vsm + CT*16);     // [CT][CT+1]
    float*  dens = ss + CT*(CT+1);
    int tid = threadIdx.x;
    int base = (bh*LL + c*CT)*DH;
    for (int idx = tid; idx < CT*16; idx += 256) {
        int row = idx >> 4, kk = idx & 15;
        qsm[row*17 + kk] = ((const float4*)(g_qf + base))[idx];
        ksm[row*16 + (kk ^ (row >> 4))] = ((const float4*)(g_kf + base))[idx];
        vsm[row*16 + kk] = ((const float4*)(g_vf + base))[idx];
    }
    __syncthreads();
    int i = tid >> 2, t4 = tid & 3;
    int jb = t4 * 16;
    // ---- phase A: scores (all pairs, each computed once) ----
    {
        float s[16] = {};
        #pragma unroll
        for (int kk = 0; kk < 16; kk++) {
            float4 q4 = qsm[i*17 + kk];
            #pragma unroll
            for (int j = 0; j < 16; j++) {
                float4 k4 = ksm[(jb + j)*16 + (kk ^ t4)];
                s[j] += q4.x*k4.x + q4.y*k4.y + q4.z*k4.z + q4.w*k4.w;
            }
        }
        #pragma unroll
        for (int j = 0; j < 16; j++) ss[i*(CT+1) + jb + j] = s[j];
    }
    __syncthreads();
    const float* zp = g_z + (bh*NC + c)*DH;
    const float* qrow = (const float*)(qsm + i*17);
    if (t4 == 0) {
        float den = 1e-6f;
        for (int d = 0; d < DH; d++) den += qrow[d] * zp[d];
        for (int j = 0; j <= i; j++) den += ss[i*(CT+1) + j];
        dens[i] = den;
    }
    __syncthreads();
    // ---- phase B ----
    const float4* Sp4 = (const float4*)(g_S + (size_t)(bh*NC + c)*DH*DH);
    float4 acc[4] = {};
    for (int d = 0; d < DH; d++) {
        float qd = qrow[d];
        #pragma unroll
        for (int r = 0; r < 4; r++) {
            float4 sv = Sp4[d*16 + t4*4 + r];
            acc[r].x += qd*sv.x; acc[r].y += qd*sv.y;
            acc[r].z += qd*sv.z; acc[r].w += qd*sv.w;
        }
    }
    for (int j = 0; j <= i; j++) {
        float s = ss[i*(CT+1) + j];
        #pragma unroll
        for (int r = 0; r < 4; r++) {
            float4 v = vsm[j*16 + t4*4 + r];
            acc[r].x += s*v.x; acc[r].y += s*v.y;
            acc[r].z += s*v.z; acc[r].w += s*v.w;
        }
    }
    float invd = __fdividef(1.0f, dens[i]);
    int b = bh / HH, h = bh - b*HH;
    int l = c*CT + i;
    size_t obase = (size_t)(b*LL + l)*DD + h*DH + t4*16;
    #pragma unroll
    for (int r = 0; r < 4; r++) {
        float o0 = acc[r].x * invd, o1 = acc[r].y * invd;
        float o2 = acc[r].z * invd, o3 = acc[r].w * invd;
        bf16 h0, l0, h1, l1, h2, l2, h3, l3;
        split2(o0, h0, l0); split2(o1, h1, l1);
        split2(o2, h2, l2); split2(o3, h3, l3);
        __nv_bfloat162 pa; pa.x = h0; pa.y = h1;
        __nv_bfloat162 pb; pb.x = h2; pb.y = h3;
        __nv_bfloat162 pc; pc.x = l0; pc.y = l1;
        __nv_bfloat162 pd; pd.x = l2; pd.y = l3;
        *(__nv_bfloat162*)(g_at0 + obase + r*4)     = pa;
        *(__nv_bfloat162*)(g_at0 + obase + r*4 + 2) = pb;
        *(__nv_bfloat162*)(g_at1 + obase + r*4)     = pc;
        *(__nv_bfloat162*)(g_at1 + obase + r*4 + 2) = pd;
    }
}

// ---------------- launch -------------------------------------------------------
extern "C" void kernel_launch(void* const* d_in, const int* in_sizes, int n_in,
                              void* d_out, int out_size) {
    const float* x          = (const float*)d_in[0];
    const float* W_qkv      = (const float*)d_in[1];
    const float* b_qkv      = (const float*)d_in[2];
    const float* W_sem_down = (const float*)d_in[3];
    const float* W_sem_up   = (const float*)d_in[4];
    const float* W_ctx_down = (const float*)d_in[5];
    const float* W_ctx_up   = (const float*)d_in[6];
    const float* temperature= (const float*)d_in[7];
    const float* W_proj     = (const float*)d_in[8];
    const float* b_proj     = (const float*)d_in[9];
    const float* gamma      = (const float*)d_in[10];
    const float* beta       = (const float*)d_in[11];
    float* y_out    = (float*)d_out;
    float* gate_out = y_out + (size_t)NROWS*DD;

    float *p_qkv, *p_sem, *p_ctx;
    bf16 *p_xn0, *p_xn1, *p_x0, *p_x1, *p_hs0, *p_hs1, *p_hc0, *p_hc1, *p_at0, *p_at1;
    bf16 *p_wq0, *p_wq1, *p_wsd0, *p_wsd1, *p_wcd0, *p_wcd1;
    bf16 *p_wsu0, *p_wsu1, *p_wcu0, *p_wcu1, *p_wp0, *p_wp1;
    cudaGetSymbolAddress((void**)&p_qkv, g_qkv);
    cudaGetSymbolAddress((void**)&p_sem, g_sem);
    cudaGetSymbolAddress((void**)&p_ctx, g_ctx);
    cudaGetSymbolAddress((void**)&p_xn0, g_xn0);  cudaGetSymbolAddress((void**)&p_xn1, g_xn1);
    cudaGetSymbolAddress((void**)&p_x0,  g_x0);   cudaGetSymbolAddress((void**)&p_x1,  g_x1);
    cudaGetSymbolAddress((void**)&p_hs0, g_hs0);  cudaGetSymbolAddress((void**)&p_hs1, g_hs1);
    cudaGetSymbolAddress((void**)&p_hc0, g_hc0);  cudaGetSymbolAddress((void**)&p_hc1, g_hc1);
    cudaGetSymbolAddress((void**)&p_at0, g_at0);  cudaGetSymbolAddress((void**)&p_at1, g_at1);
    cudaGetSymbolAddress((void**)&p_wq0, g_wq0);  cudaGetSymbolAddress((void**)&p_wq1, g_wq1);
    cudaGetSymbolAddress((void**)&p_wsd0,g_wsd0); cudaGetSymbolAddress((void**)&p_wsd1,g_wsd1);
    cudaGetSymbolAddress((void**)&p_wcd0,g_wcd0); cudaGetSymbolAddress((void**)&p_wcd1,g_wcd1);
    cudaGetSymbolAddress((void**)&p_wsu0,g_wsu0); cudaGetSymbolAddress((void**)&p_wsu1,g_wsu1);
    cudaGetSymbolAddress((void**)&p_wcu0,g_wcu0); cudaGetSymbolAddress((void**)&p_wcu1,g_wcu1);
    cudaGetSymbolAddress((void**)&p_wp0, g_wp0);  cudaGetSymbolAddress((void**)&p_wp1, g_wp1);

    constexpr int SMEM128 = 2 * (256 + 256) * ST32 * 4;   // 81920
    constexpr int SMEM64  = 2 * (256 + 128) * ST32 * 4;   // 61440

    static cudaStream_t s_side = nullptr;
    static cudaEvent_t evA = nullptr, evB = nullptr;
    static bool attr_set = false;
    if (!attr_set) {
        cudaFuncSetAttribute((const void*)bgemm_kernel<0,128>, cudaFuncAttributeMaxDynamicSharedMemorySize, SMEM128);
        cudaFuncSetAttribute((const void*)bgemm_kernel<1,128>, cudaFuncAttributeMaxDynamicSharedMemorySize, SMEM128);
        cudaFuncSetAttribute((const void*)bgemm_kernel<2,64>,  cudaFuncAttributeMaxDynamicSharedMemorySize, SMEM64);
        cudaFuncSetAttribute((const void*)attn_kernel, cudaFuncAttributeMaxDynamicSharedMemorySize, ATTN_SMEM);
        cudaStreamCreateWithFlags(&s_side, cudaStreamNonBlocking);
        cudaEventCreateWithFlags(&evA, cudaEventDisableTiming);
        cudaEventCreateWithFlags(&evB, cudaEventDisableTiming);
        attr_set = true;
    }

    // prep: weight split + layernorm/input split (one launch)
    prep_kernel<<<TP + NROWS, 256>>>(W_qkv, W_sem_down, W_ctx_down, W_sem_up,
                                     W_ctx_up, W_proj, x, gamma, beta);
    cudaEventRecord(evA, 0);
    cudaStreamWaitEvent(s_side, evA, 0);

    // main stream: qkv GEMM  (4096 x 2304 x 768)
    bgemm_kernel<1,128><<<dim3(3*DD/128, NROWS/128, 1), 256, SMEM128>>>(
        p_xn0, p_xn1, p_wq0, p_wq1, b_qkv, p_qkv, nullptr, nullptr, 3*DD, DD,
        nullptr, nullptr, nullptr, nullptr, nullptr, nullptr, nullptr);

    // side stream: down (silu, split out) then up
    bgemm_kernel<2,64><<<dim3(RR/64, NROWS/128, 2), 256, SMEM64, s_side>>>(
        p_x0, p_x1, p_wsd0, p_wsd1, nullptr, nullptr, p_hs0, p_hs1, RR, DD,
        nullptr, nullptr, p_wcd0, p_wcd1, nullptr, p_hc0, p_hc1);
    bgemm_kernel<0,128><<<dim3(2*DD/128, NROWS/128, 2), 256, SMEM128, s_side>>>(
        p_hs0, p_hs1, p_wsu0, p_wsu1, nullptr, p_sem, nullptr, nullptr, 2*DD, RR,
        p_hc0, p_hc1, p_wcu0, p_wcu1, p_ctx, nullptr, nullptr);
    cudaEventRecord(evB, s_side);
    cudaStreamWaitEvent(0, evB, 0);

    gate_kernel<<<(NROWS*DD)/256, 256>>>(temperature, gate_out);

    chunksum_kernel<<<dim3(NC, BHN), 256>>>();
    scan_kernel<<<dim3(BHN, 16), 256>>>();
    attn_kernel<<<dim3(NC, BHN), 256, ATTN_SMEM>>>();

    // y = attn @ W_proj + b_proj        (4096 x 768 x 768)
    bgemm_kernel<1,128><<<dim3(DD/128, NROWS/128, 1), 256, SMEM128>>>(
        p_at0, p_at1, p_wp0, p_wp1, b_proj, y_out, nullptr, nullptr, DD, DD,
        nullptr, nullptr, nullptr, nullptr, nullptr, nullptr, nullptr);
}

// round 13
// speedup vs baseline: 4.9900x; 1.0220x over previous
#include <cuda_runtime.h>
#include <cuda_bf16.h>
#include <math.h>
#include <stdint.h>

#define BB 2
#define LL 2048
#define DD 768
#define HH 12
#define RR 128
#define DH 64
#define NROWS (BB*LL)        // 4096
#define NC 32
#define CT 64
#define BHN (BB*HH)
#define PI_F 3.14159265358979323846f

typedef __nv_bfloat16 bf16;

// ---------------- scratch ---------------------------------------------------
__device__ float g_qkv[NROWS*3*DD];
__device__ float g_sem[NROWS*2*DD];
__device__ float g_ctx[NROWS*2*DD];
__device__ float g_qf[NROWS*DD];
__device__ float g_kf[NROWS*DD];
__device__ float g_vf[NROWS*DD];
__device__ float g_S[BHN*NC*DH*DH];
__device__ float g_z[BHN*NC*DH];

// bf16 split pairs
__device__ bf16 g_xn0[NROWS*DD], g_xn1[NROWS*DD];
__device__ bf16 g_x0[NROWS*DD],  g_x1[NROWS*DD];
__device__ bf16 g_hs0[NROWS*RR], g_hs1[NROWS*RR];
__device__ bf16 g_hc0[NROWS*RR], g_hc1[NROWS*RR];
__device__ bf16 g_at0[NROWS*DD], g_at1[NROWS*DD];
// weights, split + transposed to [N][K]
__device__ bf16 g_wq0[3*DD*DD],  g_wq1[3*DD*DD];
__device__ bf16 g_wsd0[RR*DD],   g_wsd1[RR*DD];
__device__ bf16 g_wcd0[RR*DD],   g_wcd1[RR*DD];
__device__ bf16 g_wsu0[2*DD*RR], g_wsu1[2*DD*RR];
__device__ bf16 g_wcu0[2*DD*RR], g_wcu1[2*DD*RR];
__device__ bf16 g_wp0[DD*DD],    g_wp1[DD*DD];

// ---------------- helpers ----------------------------------------------------
__device__ __forceinline__ uint32_t smem_u32p(const void* p) {
    uint32_t a;
    asm("{ .reg .u64 t; cvta.to.shared.u64 t, %1; cvt.u32.u64 %0, t; }" : "=r"(a) : "l"(p));
    return a;
}
__device__ __forceinline__ void mma_bf16(float* c, const uint32_t* a,
                                         uint32_t b0, uint32_t b1) {
    asm volatile(
        "mma.sync.aligned.m16n8k16.row.col.f32.bf16.bf16.f32 "
        "{%0,%1,%2,%3}, {%4,%5,%6,%7}, {%8,%9}, {%0,%1,%2,%3};"
        : "+f"(c[0]), "+f"(c[1]), "+f"(c[2]), "+f"(c[3])
        : "r"(a[0]), "r"(a[1]), "r"(a[2]), "r"(a[3]), "r"(b0), "r"(b1));
}
__device__ __forceinline__ void ldsm_x4(uint32_t* r, uint32_t addr) {
    asm volatile("ldmatrix.sync.aligned.m8n8.x4.shared.b16 {%0,%1,%2,%3}, [%4];"
        : "=r"(r[0]), "=r"(r[1]), "=r"(r[2]), "=r"(r[3]) : "r"(addr));
}
__device__ __forceinline__ void cp16(uint32_t sp, const void* gp) {
    asm volatile("cp.async.cg.shared.global [%0], [%1], 16;" :: "r"(sp), "l"(gp) : "memory");
}
__device__ __forceinline__ void split2(float v, bf16& h, bf16& l) {
    h = __float2bfloat16(v);
    l = __float2bfloat16(v - __bfloat162float(h));
}

// ---------------- split-bf16 GEMM (3-term, m16n8k16, ldmatrix) ----------------
#define ST32 20

template<int EPI, int TN>
__global__ void __launch_bounds__(256, 2) bgemm_kernel(
    const bf16* __restrict__ A0, const bf16* __restrict__ A1,
    const bf16* __restrict__ B0, const bf16* __restrict__ B1,
    const float* __restrict__ bias, float* __restrict__ Cf,
    bf16* __restrict__ C0, bf16* __restrict__ C1,
    int N, int K,
    const bf16* A0b, const bf16* A1b, const bf16* B0b, const bf16* B1b,
    float* Cfb, bf16* C0b, bf16* C1b) {
    constexpr int NT = TN / 16;
    constexpr int STAGE_U32 = (256 + 2 * TN) * ST32;
    if (blockIdx.z == 1) {
        if (A0b) { A0 = A0b; A1 = A1b; }
        B0 = B0b; B1 = B1b; Cf = Cfb; C0 = C0b; C1 = C1b;
    }
    extern __shared__ uint32_t smu[];
    uint32_t sbase = smem_u32p(smu);
    int tid = threadIdx.x;
    int lane = tid & 31, wid = tid >> 5;
    int wm = wid & 3, wn = wid >> 2;
    int g = lane >> 2, t4 = lane & 3;
    int m0 = blockIdx.y * 128, n0 = blockIdx.x * TN;

    // ldmatrix per-lane address components
    int a_row = wm * 32 + (lane & 15);
    int a_col = (lane >> 4) << 2;                          // u32
    int b_row = wn * (TN/2) + ((lane >> 4) << 3) + (lane & 7);
    int b_col = ((lane >> 3) & 1) << 2;                    // u32

    float c[2][NT][4];
    #pragma unroll
    for (int mt = 0; mt < 2; mt++)
        #pragma unroll
        for (int nt = 0; nt < NT; nt++)
            #pragma unroll
            for (int r = 0; r < 4; r++) c[mt][nt][r] = 0.0f;

    int nstages = K >> 5;

    auto issue = [&](int s, int buf) {
        int k0 = s << 5;
        uint32_t so = sbase + buf * (STAGE_U32 * 4);
        #pragma unroll
        for (int i = 0; i < 2; i++) {
            int ch = tid + i * 256;
            int row = ch >> 2, q = ch & 3;
            uint32_t d = so + (row * ST32 + q * 4) * 4;
            cp16(d,                 A0 + (size_t)(m0 + row) * K + k0 + q * 8);
            cp16(d + 128*ST32*4,    A1 + (size_t)(m0 + row) * K + k0 + q * 8);
        }
        #pragma unroll
        for (int i = 0; i < TN/64; i++) {
            int ch = tid + i * 256;
            int row = ch >> 2, q = ch & 3;
            uint32_t d = so + ((256 + row) * ST32 + q * 4) * 4;
            cp16(d,               B0 + (size_t)(n0 + row) * K + k0 + q * 8);
            cp16(d + TN*ST32*4,   B1 + (size_t)(n0 + row) * K + k0 + q * 8);
        }
        asm volatile("cp.async.commit_group;" ::: "memory");
    };

    issue(0, 0);
    for (int s = 0; s < nstages; s++) {
        int buf = s & 1;
        if (s + 1 < nstages) {
            issue(s + 1, buf ^ 1);
            asm volatile("cp.async.wait_group 1;" ::: "memory");
        } else {
            asm volatile("cp.async.wait_group 0;" ::: "memory");
        }
        __syncthreads();

        uint32_t stg = sbase + buf * (STAGE_U32 * 4);
        uint32_t pA0 = stg + (a_row * ST32 + a_col) * 4;
        uint32_t pA1 = pA0 + 128 * ST32 * 4;
        uint32_t pB0 = stg + ((256 + b_row) * ST32 + b_col) * 4;
        uint32_t pB1 = pB0 + TN * ST32 * 4;

        #pragma unroll
        for (int ks = 0; ks < 2; ks++) {
            int kb4 = ks * 32;                            // 8 u32 * 4B
            uint32_t a0f[2][4], a1f[2][4];
            #pragma unroll
            for (int mt = 0; mt < 2; mt++) {
                ldsm_x4(a0f[mt], pA0 + mt * (16 * ST32 * 4) + kb4);
                ldsm_x4(a1f[mt], pA1 + mt * (16 * ST32 * 4) + kb4);
            }
            #pragma unroll
            for (int ntp = 0; ntp < NT/2; ntp++) {
                uint32_t b0r[4], b1r[4];
                ldsm_x4(b0r, pB0 + ntp * (16 * ST32 * 4) + kb4);
                ldsm_x4(b1r, pB1 + ntp * (16 * ST32 * 4) + kb4);
                #pragma unroll
                for (int mt = 0; mt < 2; mt++) {
                    mma_bf16(c[mt][2*ntp],   a0f[mt], b0r[0], b0r[1]);
                    mma_bf16(c[mt][2*ntp],   a0f[mt], b1r[0], b1r[1]);
                    mma_bf16(c[mt][2*ntp],   a1f[mt], b0r[0], b0r[1]);
                    mma_bf16(c[mt][2*ntp+1], a0f[mt], b0r[2], b0r[3]);
                    mma_bf16(c[mt][2*ntp+1], a0f[mt], b1r[2], b1r[3]);
                    mma_bf16(c[mt][2*ntp+1], a1f[mt], b0r[2], b0r[3]);
                }
            }
        }
        __syncthreads();
    }

    #pragma unroll
    for (int mt = 0; mt < 2; mt++) {
        int row = m0 + wm * 32 + mt * 16 + g;
        #pragma unroll
        for (int nt = 0; nt < NT; nt++) {
            int col = n0 + wn * (TN/2) + nt * 8 + 2 * t4;
            float v0 = c[mt][nt][0], v1 = c[mt][nt][1];
            float v2 = c[mt][nt][2], v3 = c[mt][nt][3];
            if (EPI == 1) {
                float b0 = bias[col], b1 = bias[col + 1];
                v0 += b0; v1 += b1; v2 += b0; v3 += b1;
            }
            if (EPI == 2) {
                v0 = v0 * __fdividef(1.0f, 1.0f + __expf(-v0));
                v1 = v1 * __fdividef(1.0f, 1.0f + __expf(-v1));
                v2 = v2 * __fdividef(1.0f, 1.0f + __expf(-v2));
                v3 = v3 * __fdividef(1.0f, 1.0f + __expf(-v3));
                bf16 h0, l0, h1, l1, h2, l2, h3, l3;
                split2(v0, h0, l0); split2(v1, h1, l1);
                split2(v2, h2, l2); split2(v3, h3, l3);
                __nv_bfloat162 ph0; ph0.x = h0; ph0.y = h1;
                __nv_bfloat162 pl0; pl0.x = l0; pl0.y = l1;
                __nv_bfloat162 ph1; ph1.x = h2; ph1.y = h3;
                __nv_bfloat162 pl1; pl1.x = l2; pl1.y = l3;
                *(__nv_bfloat162*)(C0 + (size_t)row * N + col)       = ph0;
                *(__nv_bfloat162*)(C1 + (size_t)row * N + col)       = pl0;
                *(__nv_bfloat162*)(C0 + (size_t)(row + 8) * N + col) = ph1;
                *(__nv_bfloat162*)(C1 + (size_t)(row + 8) * N + col) = pl1;
            } else {
                *(float2*)(Cf + (size_t)row * N + col)       = make_float2(v0, v1);
                *(float2*)(Cf + (size_t)(row + 8) * N + col) = make_float2(v2, v3);
            }
        }
    }
}

// ---------------- prep: weight split + layernorm (merged) --------------------
#define TQ  1728
#define TSD (TQ + 96)
#define TCD (TSD + 96)
#define TSU (TCD + 192)
#define TCU (TSU + 192)
#define TP  (TCU + 576)
__global__ void prep_kernel(
    const float* __restrict__ Wq, const float* __restrict__ Wsd,
    const float* __restrict__ Wcd, const float* __restrict__ Wsu,
    const float* __restrict__ Wcu, const float* __restrict__ Wp,
    const float* __restrict__ x, const float* __restrict__ gamma,
    const float* __restrict__ beta) {
    int bid = blockIdx.x;
    if (bid < TP) {
        int t = bid;
        const float* W; bf16 *D0, *D1; int K, N;
        if (t < TQ)       { W = Wq;  D0 = g_wq0;  D1 = g_wq1;  K = DD;  N = 3*DD; }
        else if (t < TSD) { t -= TQ;  W = Wsd; D0 = g_wsd0; D1 = g_wsd1; K = DD;  N = RR; }
        else if (t < TCD) { t -= TSD; W = Wcd; D0 = g_wcd0; D1 = g_wcd1; K = DD;  N = RR; }
        else if (t < TSU) { t -= TCD; W = Wsu; D0 = g_wsu0; D1 = g_wsu1; K = RR;  N = 2*DD; }
        else if (t < TCU) { t -= TSU; W = Wcu; D0 = g_wcu0; D1 = g_wcu1; K = RR;  N = 2*DD; }
        else              { t -= TCU; W = Wp;  D0 = g_wp0;  D1 = g_wp1;  K = DD;  N = DD; }
        int tN = N >> 5;
        int k0 = (t / tN) << 5, n0 = (t % tN) << 5;
        __shared__ float sm[32][33];
        int tx = threadIdx.x & 31, ty = threadIdx.x >> 5;
        #pragma unroll
        for (int i = 0; i < 4; i++)
            sm[ty + 8*i][tx] = W[(size_t)(k0 + ty + 8*i) * N + n0 + tx];
        __syncthreads();
        #pragma unroll
        for (int i = 0; i < 4; i++) {
            float v = sm[tx][ty + 8*i];
            bf16 h, l; split2(v, h, l);
            size_t o = (size_t)(n0 + ty + 8*i) * K + k0 + tx;
            D0[o] = h; D1[o] = l;
        }
    } else {
        int row = bid - TP;
        const float* xr = x + (size_t)row*DD;
        int t = threadIdx.x;
        float v0 = xr[t], v1 = xr[t+256], v2 = xr[t+512];
        __shared__ float red[256], red2[256];
        red[t]  = v0+v1+v2;
        red2[t] = v0*v0+v1*v1+v2*v2;
        __syncthreads();
        for (int o = 128; o > 0; o >>= 1) {
            if (t < o) { red[t] += red[t+o]; red2[t] += red2[t+o]; }
            __syncthreads();
        }
        float mu  = red[0] * (1.0f/DD);
        float var = red2[0] * (1.0f/DD) - mu*mu;
        float inv = rsqrtf(var + 1e-5f);
        size_t base = (size_t)row*DD;
        float vv[3] = {v0, v1, v2};
        #pragma unroll
        for (int i = 0; i < 3; i++) {
            int d = t + i*256;
            float xn = (vv[i]-mu)*inv*gamma[d] + beta[d];
            bf16 h, l;
            split2(xn, h, l);    g_xn0[base+d] = h; g_xn1[base+d] = l;
            split2(vv[i], h, l); g_x0[base+d]  = h; g_x1[base+d]  = l;
        }
    }
}

// ---------------- fused gate + chunk k(x)v sums -------------------------------
__device__ __forceinline__ float softplus_f(float a) {
    return a > 15.0f ? a : __logf(1.0f + __expf(a));
}
__device__ __forceinline__ float tanh_f(float a) {
    float x = fminf(fmaxf(a, -15.0f), 15.0f);
    float t = __expf(2.0f * x);
    return __fdividef(t - 1.0f, t + 1.0f);
}
__global__ void __launch_bounds__(256) gatechunk_kernel(
    const float* __restrict__ temperature, float* __restrict__ gate_out) {
    int c = blockIdx.x, bh = blockIdx.y;
    int b = bh / HH, h = bh - b*HH;
    __shared__ float  ksm[CT][DH+1];
    __shared__ float4 vsm[CT][DH/4];
    int tid = threadIdx.x;
    int i = tid >> 2, t4 = tid & 3;
    int gr = b*LL + c*CT + i;
    int d0 = h*DH + t4*16;
    float temp = temperature[0];
    const float* sr = g_sem + (size_t)gr*(2*DD);
    const float* cr = g_ctx + (size_t)gr*(2*DD);
    const float* qr = g_qkv + (size_t)gr*(3*DD);
    size_t hidb = ((size_t)bh*LL + c*CT + i)*DH + t4*16;
    #pragma unroll
    for (int r = 0; r < 4; r++) {
        float4 sa4 = *(const float4*)(sr + d0 + r*4);
        float4 sp4 = *(const float4*)(sr + DD + d0 + r*4);
        float4 ca4 = *(const float4*)(cr + d0 + r*4);
        float4 cp4 = *(const float4*)(cr + DD + d0 + r*4);
        float4 q4  = *(const float4*)(qr + d0 + r*4);
        float4 k4  = *(const float4*)(qr + DD + d0 + r*4);
        float4 v4  = *(const float4*)(qr + 2*DD + d0 + r*4);
        float sav[4] = {sa4.x, sa4.y, sa4.z, sa4.w};
        float spv[4] = {sp4.x, sp4.y, sp4.z, sp4.w};
        float cav[4] = {ca4.x, ca4.y, ca4.z, ca4.w};
        float cpv[4] = {cp4.x, cp4.y, cp4.z, cp4.w};
        float qv[4]  = {q4.x, q4.y, q4.z, q4.w};
        float kv[4]  = {k4.x, k4.y, k4.z, k4.w};
        float gov[4], qfv[4], kfv[4];
        #pragma unroll
        for (int u = 0; u < 4; u++) {
            float sa = softplus_f(sav[u]);
            float sp = tanh_f(spv[u]) * PI_F;
            float ca = softplus_f(cav[u]);
            float cp = tanh_f(cpv[u]) * PI_F;
            float inter = sa * ca * __cosf(sp - cp) * temp;
            float gate = __fdividef(1.0f, 1.0f + __expf(-inter));
            gov[u] = gate;
            float q = qv[u];
            float k = kv[u] * (1.0f + gate);
            qfv[u] = q > 0.0f ? q + 1.0f : __expf(q);
            kfv[u] = k > 0.0f ? k + 1.0f : __expf(k);
            ksm[i][t4*16 + r*4 + u] = kfv[u];
        }
        vsm[i][t4*4 + r] = v4;
        *(float4*)(gate_out + (size_t)gr*DD + d0 + r*4) = make_float4(gov[0], gov[1], gov[2], gov[3]);
        *(float4*)(g_qf + hidb + r*4) = make_float4(qfv[0], qfv[1], qfv[2], qfv[3]);
        *(float4*)(g_kf + hidb + r*4) = make_float4(kfv[0], kfv[1], kfv[2], kfv[3]);
        *(float4*)(g_vf + hidb + r*4) = v4;
    }
    __syncthreads();
    // chunk sums: d = i, output slice = t4*16
    float4 acc[4] = {};
    float zacc = 0.0f;
    for (int l = 0; l < CT; l++) {
        float kd = ksm[l][i];
        zacc += kd;
        #pragma unroll
        for (int r = 0; r < 4; r++) {
            float4 v = vsm[l][t4*4 + r];
            acc[r].x += kd*v.x; acc[r].y += kd*v.y;
            acc[r].z += kd*v.z; acc[r].w += kd*v.w;
        }
    }
    float4* Sp = (float4*)(g_S + (size_t)(bh*NC + c)*DH*DH + i*DH + t4*16);
    #pragma unroll
    for (int r = 0; r < 4; r++) Sp[r] = acc[r];
    if (t4 == 0) g_z[(bh*NC + c)*DH + i] = zacc;
}

__global__ void scan_kernel() {
    int bh = blockIdx.x;
    int e = blockIdx.y * 256 + threadIdx.x;
    float* p = g_S + (size_t)bh*NC*DH*DH + e;
    float run = 0.0f;
    #pragma unroll
    for (int c = 0; c < NC; c++) {
        float t = p[(size_t)c*DH*DH];
        p[(size_t)c*DH*DH] = run;
        run += t;
    }
    if (blockIdx.y == 0 && threadIdx.x < DH) {
        float* pz = g_z + bh*NC*DH + threadIdx.x;
        float rz = 0.0f;
        #pragma unroll
        for (int c = 0; c < NC; c++) {
            float t = pz[c*DH];
            pz[c*DH] = rz;
            rz += t;
        }
    }
}

// attn: phase A scores once into smem, phase B triangular S·V + inter-chunk
#define ATTN_SMEM ((CT*17 + CT*16 + CT*16)*16 + CT*(CT+1)*4 + CT*4)
__global__ void __launch_bounds__(256) attn_kernel() {
    int c  = blockIdx.x;
    int bh = blockIdx.y;
    extern __shared__ char asmem[];
    float4* qsm = (float4*)asmem;            // [CT][17] padded
    float4* ksm = qsm + CT*17;               // [CT][16] xor-swizzled
    float4* vsm = ksm + CT*16;               // [CT][16]
    float*  ss  = (float*)(vsm + CT*16);     // [CT][CT+1]
    float*  dens = ss + CT*(CT+1);
    int tid = threadIdx.x;
    int base = (bh*LL + c*CT)*DH;
    for (int idx = tid; idx < CT*16; idx += 256) {
        int row = idx >> 4, kk = idx & 15;
        qsm[row*17 + kk] = ((const float4*)(g_qf + base))[idx];
        ksm[row*16 + (kk ^ (row >> 4))] = ((const float4*)(g_kf + base))[idx];
        vsm[row*16 + kk] = ((const float4*)(g_vf + base))[idx];
    }
    __syncthreads();
    int i = tid >> 2, t4 = tid & 3;
    int jb = t4 * 16;
    {
        float s[16] = {};
        #pragma unroll
        for (int kk = 0; kk < 16; kk++) {
            float4 q4 = qsm[i*17 + kk];
            #pragma unroll
            for (int j = 0; j < 16; j++) {
                float4 k4 = ksm[(jb + j)*16 + (kk ^ t4)];
                s[j] += q4.x*k4.x + q4.y*k4.y + q4.z*k4.z + q4.w*k4.w;
            }
        }
        #pragma unroll
        for (int j = 0; j < 16; j++) ss[i*(CT+1) + jb + j] = s[j];
    }
    __syncthreads();
    const float* zp = g_z + (bh*NC + c)*DH;
    const float* qrow = (const float*)(qsm + i*17);
    if (t4 == 0) {
        float den = 1e-6f;
        for (int d = 0; d < DH; d++) den += qrow[d] * zp[d];
        for (int j = 0; j <= i; j++) den += ss[i*(CT+1) + j];
        dens[i] = den;
    }
    __syncthreads();
    const float4* Sp4 = (const float4*)(g_S + (size_t)(bh*NC + c)*DH*DH);
    float4 acc[4] = {};
    for (int d = 0; d < DH; d++) {
        float qd = qrow[d];
        #pragma unroll
        for (int r = 0; r < 4; r++) {
            float4 sv = Sp4[d*16 + t4*4 + r];
            acc[r].x += qd*sv.x; acc[r].y += qd*sv.y;
            acc[r].z += qd*sv.z; acc[r].w += qd*sv.w;
        }
    }
    for (int j = 0; j <= i; j++) {
        float s = ss[i*(CT+1) + j];
        #pragma unroll
        for (int r = 0; r < 4; r++) {
            float4 v = vsm[j*16 + t4*4 + r];
            acc[r].x += s*v.x; acc[r].y += s*v.y;
            acc[r].z += s*v.z; acc[r].w += s*v.w;
        }
    }
    float invd = __fdividef(1.0f, dens[i]);
    int b = bh / HH, h = bh - b*HH;
    int l = c*CT + i;
    size_t obase = (size_t)(b*LL + l)*DD + h*DH + t4*16;
    #pragma unroll
    for (int r = 0; r < 4; r++) {
        float o0 = acc[r].x * invd, o1 = acc[r].y * invd;
        float o2 = acc[r].z * invd, o3 = acc[r].w * invd;
        bf16 h0, l0, h1, l1, h2, l2, h3, l3;
        split2(o0, h0, l0); split2(o1, h1, l1);
        split2(o2, h2, l2); split2(o3, h3, l3);
        __nv_bfloat162 pa; pa.x = h0; pa.y = h1;
        __nv_bfloat162 pb; pb.x = h2; pb.y = h3;
        __nv_bfloat162 pc; pc.x = l0; pc.y = l1;
        __nv_bfloat162 pd; pd.x = l2; pd.y = l3;
        *(__nv_bfloat162*)(g_at0 + obase + r*4)     = pa;
        *(__nv_bfloat162*)(g_at0 + obase + r*4 + 2) = pb;
        *(__nv_bfloat162*)(g_at1 + obase + r*4)     = pc;
        *(__nv_bfloat162*)(g_at1 + obase + r*4 + 2) = pd;
    }
}

// ---------------- launch -------------------------------------------------------
extern "C" void kernel_launch(void* const* d_in, const int* in_sizes, int n_in,
                              void* d_out, int out_size) {
    const float* x          = (const float*)d_in[0];
    const float* W_qkv      = (const float*)d_in[1];
    const float* b_qkv      = (const float*)d_in[2];
    const float* W_sem_down = (const float*)d_in[3];
    const float* W_sem_up   = (const float*)d_in[4];
    const float* W_ctx_down = (const float*)d_in[5];
    const float* W_ctx_up   = (const float*)d_in[6];
    const float* temperature= (const float*)d_in[7];
    const float* W_proj     = (const float*)d_in[8];
    const float* b_proj     = (const float*)d_in[9];
    const float* gamma      = (const float*)d_in[10];
    const float* beta       = (const float*)d_in[11];
    float* y_out    = (float*)d_out;
    float* gate_out = y_out + (size_t)NROWS*DD;

    float *p_qkv, *p_sem, *p_ctx;
    bf16 *p_xn0, *p_xn1, *p_x0, *p_x1, *p_hs0, *p_hs1, *p_hc0, *p_hc1, *p_at0, *p_at1;
    bf16 *p_wq0, *p_wq1, *p_wsd0, *p_wsd1, *p_wcd0, *p_wcd1;
    bf16 *p_wsu0, *p_wsu1, *p_wcu0, *p_wcu1, *p_wp0, *p_wp1;
    cudaGetSymbolAddress((void**)&p_qkv, g_qkv);
    cudaGetSymbolAddress((void**)&p_sem, g_sem);
    cudaGetSymbolAddress((void**)&p_ctx, g_ctx);
    cudaGetSymbolAddress((void**)&p_xn0, g_xn0);  cudaGetSymbolAddress((void**)&p_xn1, g_xn1);
    cudaGetSymbolAddress((void**)&p_x0,  g_x0);   cudaGetSymbolAddress((void**)&p_x1,  g_x1);
    cudaGetSymbolAddress((void**)&p_hs0, g_hs0);  cudaGetSymbolAddress((void**)&p_hs1, g_hs1);
    cudaGetSymbolAddress((void**)&p_hc0, g_hc0);  cudaGetSymbolAddress((void**)&p_hc1, g_hc1);
    cudaGetSymbolAddress((void**)&p_at0, g_at0);  cudaGetSymbolAddress((void**)&p_at1, g_at1);
    cudaGetSymbolAddress((void**)&p_wq0, g_wq0);  cudaGetSymbolAddress((void**)&p_wq1, g_wq1);
    cudaGetSymbolAddress((void**)&p_wsd0,g_wsd0); cudaGetSymbolAddress((void**)&p_wsd1,g_wsd1);
    cudaGetSymbolAddress((void**)&p_wcd0,g_wcd0); cudaGetSymbolAddress((void**)&p_wcd1,g_wcd1);
    cudaGetSymbolAddress((void**)&p_wsu0,g_wsu0); cudaGetSymbolAddress((void**)&p_wsu1,g_wsu1);
    cudaGetSymbolAddress((void**)&p_wcu0,g_wcu0); cudaGetSymbolAddress((void**)&p_wcu1,g_wcu1);
    cudaGetSymbolAddress((void**)&p_wp0, g_wp0);  cudaGetSymbolAddress((void**)&p_wp1, g_wp1);

    constexpr int SMEM128 = 2 * (256 + 256) * ST32 * 4;   // 81920
    constexpr int SMEM64  = 2 * (256 + 128) * ST32 * 4;   // 61440

    static cudaStream_t s_side = nullptr;
    static cudaEvent_t evA = nullptr, evB = nullptr;
    static bool attr_set = false;
    if (!attr_set) {
        cudaFuncSetAttribute((const void*)bgemm_kernel<0,128>, cudaFuncAttributeMaxDynamicSharedMemorySize, SMEM128);
        cudaFuncSetAttribute((const void*)bgemm_kernel<1,128>, cudaFuncAttributeMaxDynamicSharedMemorySize, SMEM128);
        cudaFuncSetAttribute((const void*)bgemm_kernel<2,64>,  cudaFuncAttributeMaxDynamicSharedMemorySize, SMEM64);
        cudaFuncSetAttribute((const void*)attn_kernel, cudaFuncAttributeMaxDynamicSharedMemorySize, ATTN_SMEM);
        cudaStreamCreateWithFlags(&s_side, cudaStreamNonBlocking);
        cudaEventCreateWithFlags(&evA, cudaEventDisableTiming);
        cudaEventCreateWithFlags(&evB, cudaEventDisableTiming);
        attr_set = true;
    }

    // prep: weight split + layernorm/input split (one launch)
    prep_kernel<<<TP + NROWS, 256>>>(W_qkv, W_sem_down, W_ctx_down, W_sem_up,
                                     W_ctx_up, W_proj, x, gamma, beta);
    cudaEventRecord(evA, 0);
    cudaStreamWaitEvent(s_side, evA, 0);

    // main stream: qkv GEMM  (4096 x 2304 x 768)
    bgemm_kernel<1,128><<<dim3(3*DD/128, NROWS/128, 1), 256, SMEM128>>>(
        p_xn0, p_xn1, p_wq0, p_wq1, b_qkv, p_qkv, nullptr, nullptr, 3*DD, DD,
        nullptr, nullptr, nullptr, nullptr, nullptr, nullptr, nullptr);

    // side stream: down (silu, split out) then up
    bgemm_kernel<2,64><<<dim3(RR/64, NROWS/128, 2), 256, SMEM64, s_side>>>(
        p_x0, p_x1, p_wsd0, p_wsd1, nullptr, nullptr, p_hs0, p_hs1, RR, DD,
        nullptr, nullptr, p_wcd0, p_wcd1, nullptr, p_hc0, p_hc1);
    bgemm_kernel<0,128><<<dim3(2*DD/128, NROWS/128, 2), 256, SMEM128, s_side>>>(
        p_hs0, p_hs1, p_wsu0, p_wsu1, nullptr, p_sem, nullptr, nullptr, 2*DD, RR,
        p_hc0, p_hc1, p_wcu0, p_wcu1, p_ctx, nullptr, nullptr);
    cudaEventRecord(evB, s_side);
    cudaStreamWaitEvent(0, evB, 0);

    // fused gate + chunk sums
    gatechunk_kernel<<<dim3(NC, BHN), 256>>>(temperature, gate_out);
    scan_kernel<<<dim3(BHN, 16), 256>>>();
    attn_kernel<<<dim3(NC, BHN), 256, ATTN_SMEM>>>();

    // y = attn @ W_proj + b_proj        (4096 x 768 x 768)
    bgemm_kernel<1,128><<<dim3(DD/128, NROWS/128, 1), 256, SMEM128>>>(
        p_at0, p_at1, p_wp0, p_wp1, b_proj, y_out, nullptr, nullptr, DD, DD,
        nullptr, nullptr, nullptr, nullptr, nullptr, nullptr, nullptr);
}

// round 14
// speedup vs baseline: 6.1440x; 1.2313x over previous
#include <cuda_runtime.h>
#include <cuda_bf16.h>
#include <math.h>
#include <stdint.h>

#define BB 2
#define LL 2048
#define DD 768
#define HH 12
#define RR 128
#define DH 64
#define NROWS (BB*LL)        // 4096
#define NC 32
#define CT 64
#define BHN (BB*HH)
#define PI_F 3.14159265358979323846f

typedef __nv_bfloat16 bf16;

// ---------------- scratch ---------------------------------------------------
__device__ float g_qkv[NROWS*3*DD];
__device__ float g_sem[NROWS*2*DD];
__device__ float g_ctx[NROWS*2*DD];
__device__ float g_kf[NROWS*DD];
__device__ float g_S[BHN*NC*DH*DH];
__device__ float g_z[BHN*NC*DH];

// bf16 split pairs
__device__ bf16 g_xn0[NROWS*DD], g_xn1[NROWS*DD];
__device__ bf16 g_x0[NROWS*DD],  g_x1[NROWS*DD];
__device__ bf16 g_hs0[NROWS*RR], g_hs1[NROWS*RR];
__device__ bf16 g_hc0[NROWS*RR], g_hc1[NROWS*RR];
__device__ bf16 g_at0[NROWS*DD], g_at1[NROWS*DD];
// weights, split + transposed to [N][K]
__device__ bf16 g_wq0[3*DD*DD],  g_wq1[3*DD*DD];
__device__ bf16 g_wsd0[RR*DD],   g_wsd1[RR*DD];
__device__ bf16 g_wcd0[RR*DD],   g_wcd1[RR*DD];
__device__ bf16 g_wsu0[2*DD*RR], g_wsu1[2*DD*RR];
__device__ bf16 g_wcu0[2*DD*RR], g_wcu1[2*DD*RR];
__device__ bf16 g_wp0[DD*DD],    g_wp1[DD*DD];

// ---------------- helpers ----------------------------------------------------
__device__ __forceinline__ uint32_t smem_u32p(const void* p) {
    uint32_t a;
    asm("{ .reg .u64 t; cvta.to.shared.u64 t, %1; cvt.u32.u64 %0, t; }" : "=r"(a) : "l"(p));
    return a;
}
__device__ __forceinline__ void mma_bf16(float* c, const uint32_t* a,
                                         uint32_t b0, uint32_t b1) {
    asm volatile(
        "mma.sync.aligned.m16n8k16.row.col.f32.bf16.bf16.f32 "
        "{%0,%1,%2,%3}, {%4,%5,%6,%7}, {%8,%9}, {%0,%1,%2,%3};"
        : "+f"(c[0]), "+f"(c[1]), "+f"(c[2]), "+f"(c[3])
        : "r"(a[0]), "r"(a[1]), "r"(a[2]), "r"(a[3]), "r"(b0), "r"(b1));
}
__device__ __forceinline__ void ldsm_x4(uint32_t* r, uint32_t addr) {
    asm volatile("ldmatrix.sync.aligned.m8n8.x4.shared.b16 {%0,%1,%2,%3}, [%4];"
        : "=r"(r[0]), "=r"(r[1]), "=r"(r[2]), "=r"(r[3]) : "r"(addr));
}
__device__ __forceinline__ void cp16(uint32_t sp, const void* gp) {
    asm volatile("cp.async.cg.shared.global [%0], [%1], 16;" :: "r"(sp), "l"(gp) : "memory");
}
__device__ __forceinline__ void split2(float v, bf16& h, bf16& l) {
    h = __float2bfloat16(v);
    l = __float2bfloat16(v - __bfloat162float(h));
}

// ---------------- split-bf16 GEMM (3-term, m16n8k16, ldmatrix) ----------------
#define ST32 20

template<int EPI, int TN>
__global__ void __launch_bounds__(256, 2) bgemm_kernel(
    const bf16* __restrict__ A0, const bf16* __restrict__ A1,
    const bf16* __restrict__ B0, const bf16* __restrict__ B1,
    const float* __restrict__ bias, float* __restrict__ Cf,
    bf16* __restrict__ C0, bf16* __restrict__ C1,
    int N, int K,
    const bf16* A0b, const bf16* A1b, const bf16* B0b, const bf16* B1b,
    float* Cfb, bf16* C0b, bf16* C1b) {
    constexpr int NT = TN / 16;
    constexpr int STAGE_U32 = (256 + 2 * TN) * ST32;
    if (blockIdx.z == 1) {
        if (A0b) { A0 = A0b; A1 = A1b; }
        B0 = B0b; B1 = B1b; Cf = Cfb; C0 = C0b; C1 = C1b;
    }
    extern __shared__ uint32_t smu[];
    uint32_t sbase = smem_u32p(smu);
    int tid = threadIdx.x;
    int lane = tid & 31, wid = tid >> 5;
    int wm = wid & 3, wn = wid >> 2;
    int g = lane >> 2, t4 = lane & 3;
    int m0 = blockIdx.y * 128, n0 = blockIdx.x * TN;

    int a_row = wm * 32 + (lane & 15);
    int a_col = (lane >> 4) << 2;
    int b_row = wn * (TN/2) + ((lane >> 4) << 3) + (lane & 7);
    int b_col = ((lane >> 3) & 1) << 2;

    float c[2][NT][4];
    #pragma unroll
    for (int mt = 0; mt < 2; mt++)
        #pragma unroll
        for (int nt = 0; nt < NT; nt++)
            #pragma unroll
            for (int r = 0; r < 4; r++) c[mt][nt][r] = 0.0f;

    int nstages = K >> 5;

    auto issue = [&](int s, int buf) {
        int k0 = s << 5;
        uint32_t so = sbase + buf * (STAGE_U32 * 4);
        #pragma unroll
        for (int i = 0; i < 2; i++) {
            int ch = tid + i * 256;
            int row = ch >> 2, q = ch & 3;
            uint32_t d = so + (row * ST32 + q * 4) * 4;
            cp16(d,                 A0 + (size_t)(m0 + row) * K + k0 + q * 8);
            cp16(d + 128*ST32*4,    A1 + (size_t)(m0 + row) * K + k0 + q * 8);
        }
        #pragma unroll
        for (int i = 0; i < TN/64; i++) {
            int ch = tid + i * 256;
            int row = ch >> 2, q = ch & 3;
            uint32_t d = so + ((256 + row) * ST32 + q * 4) * 4;
            cp16(d,               B0 + (size_t)(n0 + row) * K + k0 + q * 8);
            cp16(d + TN*ST32*4,   B1 + (size_t)(n0 + row) * K + k0 + q * 8);
        }
        asm volatile("cp.async.commit_group;" ::: "memory");
    };

    issue(0, 0);
    for (int s = 0; s < nstages; s++) {
        int buf = s & 1;
        if (s + 1 < nstages) {
            issue(s + 1, buf ^ 1);
            asm volatile("cp.async.wait_group 1;" ::: "memory");
        } else {
            asm volatile("cp.async.wait_group 0;" ::: "memory");
        }
        __syncthreads();

        uint32_t stg = sbase + buf * (STAGE_U32 * 4);
        uint32_t pA0 = stg + (a_row * ST32 + a_col) * 4;
        uint32_t pA1 = pA0 + 128 * ST32 * 4;
        uint32_t pB0 = stg + ((256 + b_row) * ST32 + b_col) * 4;
        uint32_t pB1 = pB0 + TN * ST32 * 4;

        #pragma unroll
        for (int ks = 0; ks < 2; ks++) {
            int kb4 = ks * 32;
            uint32_t a0f[2][4], a1f[2][4];
            #pragma unroll
            for (int mt = 0; mt < 2; mt++) {
                ldsm_x4(a0f[mt], pA0 + mt * (16 * ST32 * 4) + kb4);
                ldsm_x4(a1f[mt], pA1 + mt * (16 * ST32 * 4) + kb4);
            }
            #pragma unroll
            for (int ntp = 0; ntp < NT/2; ntp++) {
                uint32_t b0r[4], b1r[4];
                ldsm_x4(b0r, pB0 + ntp * (16 * ST32 * 4) + kb4);
                ldsm_x4(b1r, pB1 + ntp * (16 * ST32 * 4) + kb4);
                #pragma unroll
                for (int mt = 0; mt < 2; mt++) {
                    mma_bf16(c[mt][2*ntp],   a0f[mt], b0r[0], b0r[1]);
                    mma_bf16(c[mt][2*ntp],   a0f[mt], b1r[0], b1r[1]);
                    mma_bf16(c[mt][2*ntp],   a1f[mt], b0r[0], b0r[1]);
                    mma_bf16(c[mt][2*ntp+1], a0f[mt], b0r[2], b0r[3]);
                    mma_bf16(c[mt][2*ntp+1], a0f[mt], b1r[2], b1r[3]);
                    mma_bf16(c[mt][2*ntp+1], a1f[mt], b0r[2], b0r[3]);
                }
            }
        }
        __syncthreads();
    }

    #pragma unroll
    for (int mt = 0; mt < 2; mt++) {
        int row = m0 + wm * 32 + mt * 16 + g;
        #pragma unroll
        for (int nt = 0; nt < NT; nt++) {
            int col = n0 + wn * (TN/2) + nt * 8 + 2 * t4;
            float v0 = c[mt][nt][0], v1 = c[mt][nt][1];
            float v2 = c[mt][nt][2], v3 = c[mt][nt][3];
            if (EPI == 1) {
                float b0 = bias[col], b1 = bias[col + 1];
                v0 += b0; v1 += b1; v2 += b0; v3 += b1;
            }
            if (EPI == 2) {
                v0 = v0 * __fdividef(1.0f, 1.0f + __expf(-v0));
                v1 = v1 * __fdividef(1.0f, 1.0f + __expf(-v1));
                v2 = v2 * __fdividef(1.0f, 1.0f + __expf(-v2));
                v3 = v3 * __fdividef(1.0f, 1.0f + __expf(-v3));
                bf16 h0, l0, h1, l1, h2, l2, h3, l3;
                split2(v0, h0, l0); split2(v1, h1, l1);
                split2(v2, h2, l2); split2(v3, h3, l3);
                __nv_bfloat162 ph0; ph0.x = h0; ph0.y = h1;
                __nv_bfloat162 pl0; pl0.x = l0; pl0.y = l1;
                __nv_bfloat162 ph1; ph1.x = h2; ph1.y = h3;
                __nv_bfloat162 pl1; pl1.x = l2; pl1.y = l3;
                *(__nv_bfloat162*)(C0 + (size_t)row * N + col)       = ph0;
                *(__nv_bfloat162*)(C1 + (size_t)row * N + col)       = pl0;
                *(__nv_bfloat162*)(C0 + (size_t)(row + 8) * N + col) = ph1;
                *(__nv_bfloat162*)(C1 + (size_t)(row + 8) * N + col) = pl1;
            } else {
                *(float2*)(Cf + (size_t)row * N + col)       = make_float2(v0, v1);
                *(float2*)(Cf + (size_t)(row + 8) * N + col) = make_float2(v2, v3);
            }
        }
    }
}

// ---------------- prep: weight split + layernorm (merged) --------------------
#define TQ  1728
#define TSD (TQ + 96)
#define TCD (TSD + 96)
#define TSU (TCD + 192)
#define TCU (TSU + 192)
#define TP  (TCU + 576)
__global__ void prep_kernel(
    const float* __restrict__ Wq, const float* __restrict__ Wsd,
    const float* __restrict__ Wcd, const float* __restrict__ Wsu,
    const float* __restrict__ Wcu, const float* __restrict__ Wp,
    const float* __restrict__ x, const float* __restrict__ gamma,
    const float* __restrict__ beta) {
    int bid = blockIdx.x;
    if (bid < TP) {
        int t = bid;
        const float* W; bf16 *D0, *D1; int K, N;
        if (t < TQ)       { W = Wq;  D0 = g_wq0;  D1 = g_wq1;  K = DD;  N = 3*DD; }
        else if (t < TSD) { t -= TQ;  W = Wsd; D0 = g_wsd0; D1 = g_wsd1; K = DD;  N = RR; }
        else if (t < TCD) { t -= TSD; W = Wcd; D0 = g_wcd0; D1 = g_wcd1; K = DD;  N = RR; }
        else if (t < TSU) { t -= TCD; W = Wsu; D0 = g_wsu0; D1 = g_wsu1; K = RR;  N = 2*DD; }
        else if (t < TCU) { t -= TSU; W = Wcu; D0 = g_wcu0; D1 = g_wcu1; K = RR;  N = 2*DD; }
        else              { t -= TCU; W = Wp;  D0 = g_wp0;  D1 = g_wp1;  K = DD;  N = DD; }
        int tN = N >> 5;
        int k0 = (t / tN) << 5, n0 = (t % tN) << 5;
        __shared__ float sm[32][33];
        int tx = threadIdx.x & 31, ty = threadIdx.x >> 5;
        #pragma unroll
        for (int i = 0; i < 4; i++)
            sm[ty + 8*i][tx] = W[(size_t)(k0 + ty + 8*i) * N + n0 + tx];
        __syncthreads();
        #pragma unroll
        for (int i = 0; i < 4; i++) {
            float v = sm[tx][ty + 8*i];
            bf16 h, l; split2(v, h, l);
            size_t o = (size_t)(n0 + ty + 8*i) * K + k0 + tx;
            D0[o] = h; D1[o] = l;
        }
    } else {
        int row = bid - TP;
        const float* xr = x + (size_t)row*DD;
        int t = threadIdx.x;
        float v0 = xr[t], v1 = xr[t+256], v2 = xr[t+512];
        __shared__ float red[256], red2[256];
        red[t]  = v0+v1+v2;
        red2[t] = v0*v0+v1*v1+v2*v2;
        __syncthreads();
        for (int o = 128; o > 0; o >>= 1) {
            if (t < o) { red[t] += red[t+o]; red2[t] += red2[t+o]; }
            __syncthreads();
        }
        float mu  = red[0] * (1.0f/DD);
        float var = red2[0] * (1.0f/DD) - mu*mu;
        float inv = rsqrtf(var + 1e-5f);
        size_t base = (size_t)row*DD;
        float vv[3] = {v0, v1, v2};
        #pragma unroll
        for (int i = 0; i < 3; i++) {
            int d = t + i*256;
            float xn = (vv[i]-mu)*inv*gamma[d] + beta[d];
            bf16 h, l;
            split2(xn, h, l);    g_xn0[base+d] = h; g_xn1[base+d] = l;
            split2(vv[i], h, l); g_x0[base+d]  = h; g_x1[base+d]  = l;
        }
    }
}

// ---------------- fused gate + chunk k(x)v sums -------------------------------
__device__ __forceinline__ float softplus_f(float a) {
    return a > 15.0f ? a : __logf(1.0f + __expf(a));
}
__device__ __forceinline__ float tanh_f(float a) {
    float x = fminf(fmaxf(a, -15.0f), 15.0f);
    float t = __expf(2.0f * x);
    return __fdividef(t - 1.0f, t + 1.0f);
}
__global__ void __launch_bounds__(256) gatechunk_kernel(
    const float* __restrict__ temperature, float* __restrict__ gate_out) {
    int c = blockIdx.x, bh = blockIdx.y;
    int b = bh / HH, h = bh - b*HH;
    __shared__ float  ksm[CT][DH+1];
    __shared__ float4 vsm[CT][DH/4];
    int tid = threadIdx.x;
    int i = tid >> 2, t4 = tid & 3;
    int gr = b*LL + c*CT + i;
    int d0 = h*DH + t4*16;
    float temp = temperature[0];
    const float* sr = g_sem + (size_t)gr*(2*DD);
    const float* cr = g_ctx + (size_t)gr*(2*DD);
    const float* qr = g_qkv + (size_t)gr*(3*DD);
    size_t hidb = ((size_t)bh*LL + c*CT + i)*DH + t4*16;
    #pragma unroll
    for (int r = 0; r < 4; r++) {
        float4 sa4 = *(const float4*)(sr + d0 + r*4);
        float4 sp4 = *(const float4*)(sr + DD + d0 + r*4);
        float4 ca4 = *(const float4*)(cr + d0 + r*4);
        float4 cp4 = *(const float4*)(cr + DD + d0 + r*4);
        float4 k4  = *(const float4*)(qr + DD + d0 + r*4);
        float4 v4  = *(const float4*)(qr + 2*DD + d0 + r*4);
        float sav[4] = {sa4.x, sa4.y, sa4.z, sa4.w};
        float spv[4] = {sp4.x, sp4.y, sp4.z, sp4.w};
        float cav[4] = {ca4.x, ca4.y, ca4.z, ca4.w};
        float cpv[4] = {cp4.x, cp4.y, cp4.z, cp4.w};
        float kv[4]  = {k4.x, k4.y, k4.z, k4.w};
        float gov[4], kfv[4];
        #pragma unroll
        for (int u = 0; u < 4; u++) {
            float sa = softplus_f(sav[u]);
            float sp = tanh_f(spv[u]) * PI_F;
            float ca = softplus_f(cav[u]);
            float cp = tanh_f(cpv[u]) * PI_F;
            float inter = sa * ca * __cosf(sp - cp) * temp;
            float gate = __fdividef(1.0f, 1.0f + __expf(-inter));
            gov[u] = gate;
            float k = kv[u] * (1.0f + gate);
            kfv[u] = k > 0.0f ? k + 1.0f : __expf(k);
            ksm[i][t4*16 + r*4 + u] = kfv[u];
        }
        vsm[i][t4*4 + r] = v4;
        *(float4*)(gate_out + (size_t)gr*DD + d0 + r*4) = make_float4(gov[0], gov[1], gov[2], gov[3]);
        *(float4*)(g_kf + hidb + r*4) = make_float4(kfv[0], kfv[1], kfv[2], kfv[3]);
    }
    __syncthreads();
    // chunk sums: d = i, output slice = t4*16
    float4 acc[4] = {};
    float zacc = 0.0f;
    for (int l = 0; l < CT; l++) {
        float kd = ksm[l][i];
        zacc += kd;
        #pragma unroll
        for (int r = 0; r < 4; r++) {
            float4 v = vsm[l][t4*4 + r];
            acc[r].x += kd*v.x; acc[r].y += kd*v.y;
            acc[r].z += kd*v.z; acc[r].w += kd*v.w;
        }
    }
    float4* Sp = (float4*)(g_S + (size_t)(bh*NC + c)*DH*DH + i*DH + t4*16);
    #pragma unroll
    for (int r = 0; r < 4; r++) Sp[r] = acc[r];
    if (t4 == 0) g_z[(bh*NC + c)*DH + i] = zacc;
}

__global__ void scan_kernel() {
    int bh = blockIdx.x;
    int e = blockIdx.y * 256 + threadIdx.x;
    float* p = g_S + (size_t)bh*NC*DH*DH + e;
    float run = 0.0f;
    #pragma unroll
    for (int c = 0; c < NC; c++) {
        float t = p[(size_t)c*DH*DH];
        p[(size_t)c*DH*DH] = run;
        run += t;
    }
    if (blockIdx.y == 0 && threadIdx.x < DH) {
        float* pz = g_z + bh*NC*DH + threadIdx.x;
        float rz = 0.0f;
        #pragma unroll
        for (int c = 0; c < NC; c++) {
            float t = pz[c*DH];
            pz[c*DH] = rz;
            rz += t;
        }
    }
}

// attn: register-blocked scores + triangular S·V + inter-chunk contraction.
// smem: qsm [CT][17]f4, ksm [CT][16]f4 (kk^((row>>2)&15) swizzle), vsm [CT][16]f4,
//       ss [CT][68]f, dens [CT]f
#define ATTN_SMEM ((CT*17 + CT*16 + CT*16)*16 + CT*68*4 + CT*4)
__global__ void __launch_bounds__(256) attn_kernel() {
    int c  = blockIdx.x;
    int bh = blockIdx.y;
    int b = bh / HH, h = bh - b*HH;
    extern __shared__ char asmem[];
    float4* qsm = (float4*)asmem;
    float4* ksm = qsm + CT*17;
    float4* vsm = ksm + CT*16;
    float*  ss  = (float*)(vsm + CT*16);
    float*  dens = ss + CT*68;
    int tid = threadIdx.x;

    // load: q (elu+1) and v straight from g_qkv; k (gated) from g_kf
    for (int idx = tid; idx < CT*16; idx += 256) {
        int row = idx >> 4, kk = idx & 15;
        int gr = b*LL + c*CT + row;
        const float* qk = g_qkv + (size_t)gr*(3*DD) + h*DH;
        float4 q4 = *(const float4*)(qk + kk*4);
        q4.x = q4.x > 0.0f ? q4.x + 1.0f : __expf(q4.x);
        q4.y = q4.y > 0.0f ? q4.y + 1.0f : __expf(q4.y);
        q4.z = q4.z > 0.0f ? q4.z + 1.0f : __expf(q4.z);
        q4.w = q4.w > 0.0f ? q4.w + 1.0f : __expf(q4.w);
        qsm[row*17 + kk] = q4;
        vsm[row*16 + kk] = *(const float4*)(qk + 2*DD + kk*4);
        float4 k4 = *(const float4*)(g_kf + ((size_t)bh*LL + c*CT + row)*DH + kk*4);
        ksm[row*16 + (kk ^ ((row >> 2) & 15))] = k4;
    }
    __syncthreads();

    int ti = tid >> 4, tj = tid & 15;
    // ---- phase A: 4x4 score tile per thread ----
    {
        float s[4][4] = {};
        #pragma unroll
        for (int kk = 0; kk < 16; kk++) {
            float4 qv[4], kv[4];
            #pragma unroll
            for (int ir = 0; ir < 4; ir++) qv[ir] = qsm[(4*ti + ir)*17 + kk];
            #pragma unroll
            for (int jc = 0; jc < 4; jc++) kv[jc] = ksm[(4*tj + jc)*16 + (kk ^ tj)];
            #pragma unroll
            for (int ir = 0; ir < 4; ir++)
                #pragma unroll
                for (int jc = 0; jc < 4; jc++)
                    s[ir][jc] += qv[ir].x*kv[jc].x + qv[ir].y*kv[jc].y
                               + qv[ir].z*kv[jc].z + qv[ir].w*kv[jc].w;
        }
        #pragma unroll
        for (int ir = 0; ir < 4; ir++)
            *(float4*)(ss + (4*ti + ir)*68 + 4*tj) =
                make_float4(s[ir][0], s[ir][1], s[ir][2], s[ir][3]);
    }
    __syncthreads();
    // ---- denominators (64 threads) ----
    if (tid < CT) {
        const float* zp = g_z + (bh*NC + c)*DH;
        const float* qr = (const float*)qsm + tid*68;
        float den = 1e-6f;
        #pragma unroll 8
        for (int d = 0; d < DH; d++) den += qr[d] * zp[d];
        for (int j = 0; j <= tid; j++) den += ss[tid*68 + j];
        dens[tid] = den;
    }
    __syncthreads();
    // ---- phase B: rows 4ti..4ti+3, col float4 tj ----
    const float* Sg = g_S + (size_t)(bh*NC + c)*DH*DH;
    const float* qb = (const float*)qsm;
    float4 acc[4] = {};
    #pragma unroll 8
    for (int kk = 0; kk < DH; kk++) {
        float4 Sv = *(const float4*)(Sg + kk*DH + tj*4);
        #pragma unroll
        for (int ir = 0; ir < 4; ir++) {
            float qd = qb[(4*ti + ir)*68 + kk];
            acc[ir].x += qd*Sv.x; acc[ir].y += qd*Sv.y;
            acc[ir].z += qd*Sv.z; acc[ir].w += qd*Sv.w;
        }
    }
    int jfull = 4*ti;
    for (int j = 0; j < jfull; j++) {
        float4 vv = vsm[j*16 + tj];
        #pragma unroll
        for (int ir = 0; ir < 4; ir++) {
            float sv = ss[(4*ti + ir)*68 + j];
            acc[ir].x += sv*vv.x; acc[ir].y += sv*vv.y;
            acc[ir].z += sv*vv.z; acc[ir].w += sv*vv.w;
        }
    }
    #pragma unroll
    for (int e = 0; e < 4; e++) {
        int j = jfull + e;
        float4 vv = vsm[j*16 + tj];
        #pragma unroll
        for (int ir = 0; ir < 4; ir++) {
            float sv = (ir >= e) ? ss[(4*ti + ir)*68 + j] : 0.0f;
            acc[ir].x += sv*vv.x; acc[ir].y += sv*vv.y;
            acc[ir].z += sv*vv.z; acc[ir].w += sv*vv.w;
        }
    }
    // ---- normalize + split-store ----
    #pragma unroll
    for (int ir = 0; ir < 4; ir++) {
        int row = 4*ti + ir;
        float invd = __fdividef(1.0f, dens[row]);
        float o0 = acc[ir].x * invd, o1 = acc[ir].y * invd;
        float o2 = acc[ir].z * invd, o3 = acc[ir].w * invd;
        bf16 h0, l0, h1, l1, h2, l2, h3, l3;
        split2(o0, h0, l0); split2(o1, h1, l1);
        split2(o2, h2, l2); split2(o3, h3, l3);
        __nv_bfloat162 pa; pa.x = h0; pa.y = h1;
        __nv_bfloat162 pb; pb.x = h2; pb.y = h3;
        __nv_bfloat162 pc; pc.x = l0; pc.y = l1;
        __nv_bfloat162 pd; pd.x = l2; pd.y = l3;
        size_t obase = (size_t)(b*LL + c*CT + row)*DD + h*DH + tj*4;
        *(__nv_bfloat162*)(g_at0 + obase)     = pa;
        *(__nv_bfloat162*)(g_at0 + obase + 2) = pb;
        *(__nv_bfloat162*)(g_at1 + obase)     = pc;
        *(__nv_bfloat162*)(g_at1 + obase + 2) = pd;
    }
}

// ---------------- launch -------------------------------------------------------
extern "C" void kernel_launch(void* const* d_in, const int* in_sizes, int n_in,
                              void* d_out, int out_size) {
    const float* x          = (const float*)d_in[0];
    const float* W_qkv      = (const float*)d_in[1];
    const float* b_qkv      = (const float*)d_in[2];
    const float* W_sem_down = (const float*)d_in[3];
    const float* W_sem_up   = (const float*)d_in[4];
    const float* W_ctx_down = (const float*)d_in[5];
    const float* W_ctx_up   = (const float*)d_in[6];
    const float* temperature= (const float*)d_in[7];
    const float* W_proj     = (const float*)d_in[8];
    const float* b_proj     = (const float*)d_in[9];
    const float* gamma      = (const float*)d_in[10];
    const float* beta       = (const float*)d_in[11];
    float* y_out    = (float*)d_out;
    float* gate_out = y_out + (size_t)NROWS*DD;

    float *p_qkv, *p_sem, *p_ctx;
    bf16 *p_xn0, *p_xn1, *p_x0, *p_x1, *p_hs0, *p_hs1, *p_hc0, *p_hc1, *p_at0, *p_at1;
    bf16 *p_wq0, *p_wq1, *p_wsd0, *p_wsd1, *p_wcd0, *p_wcd1;
    bf16 *p_wsu0, *p_wsu1, *p_wcu0, *p_wcu1, *p_wp0, *p_wp1;
    cudaGetSymbolAddress((void**)&p_qkv, g_qkv);
    cudaGetSymbolAddress((void**)&p_sem, g_sem);
    cudaGetSymbolAddress((void**)&p_ctx, g_ctx);
    cudaGetSymbolAddress((void**)&p_xn0, g_xn0);  cudaGetSymbolAddress((void**)&p_xn1, g_xn1);
    cudaGetSymbolAddress((void**)&p_x0,  g_x0);   cudaGetSymbolAddress((void**)&p_x1,  g_x1);
    cudaGetSymbolAddress((void**)&p_hs0, g_hs0);  cudaGetSymbolAddress((void**)&p_hs1, g_hs1);
    cudaGetSymbolAddress((void**)&p_hc0, g_hc0);  cudaGetSymbolAddress((void**)&p_hc1, g_hc1);
    cudaGetSymbolAddress((void**)&p_at0, g_at0);  cudaGetSymbolAddress((void**)&p_at1, g_at1);
    cudaGetSymbolAddress((void**)&p_wq0, g_wq0);  cudaGetSymbolAddress((void**)&p_wq1, g_wq1);
    cudaGetSymbolAddress((void**)&p_wsd0,g_wsd0); cudaGetSymbolAddress((void**)&p_wsd1,g_wsd1);
    cudaGetSymbolAddress((void**)&p_wcd0,g_wcd0); cudaGetSymbolAddress((void**)&p_wcd1,g_wcd1);
    cudaGetSymbolAddress((void**)&p_wsu0,g_wsu0); cudaGetSymbolAddress((void**)&p_wsu1,g_wsu1);
    cudaGetSymbolAddress((void**)&p_wcu0,g_wcu0); cudaGetSymbolAddress((void**)&p_wcu1,g_wcu1);
    cudaGetSymbolAddress((void**)&p_wp0, g_wp0);  cudaGetSymbolAddress((void**)&p_wp1, g_wp1);

    constexpr int SMEM128 = 2 * (256 + 256) * ST32 * 4;   // 81920
    constexpr int SMEM64  = 2 * (256 + 128) * ST32 * 4;   // 61440

    static cudaStream_t s_side = nullptr;
    static cudaEvent_t evA = nullptr, evB = nullptr;
    static bool attr_set = false;
    if (!attr_set) {
        cudaFuncSetAttribute((const void*)bgemm_kernel<0,128>, cudaFuncAttributeMaxDynamicSharedMemorySize, SMEM128);
        cudaFuncSetAttribute((const void*)bgemm_kernel<1,128>, cudaFuncAttributeMaxDynamicSharedMemorySize, SMEM128);
        cudaFuncSetAttribute((const void*)bgemm_kernel<2,64>,  cudaFuncAttributeMaxDynamicSharedMemorySize, SMEM64);
        cudaFuncSetAttribute((const void*)attn_kernel, cudaFuncAttributeMaxDynamicSharedMemorySize, ATTN_SMEM);
        cudaStreamCreateWithFlags(&s_side, cudaStreamNonBlocking);
        cudaEventCreateWithFlags(&evA, cudaEventDisableTiming);
        cudaEventCreateWithFlags(&evB, cudaEventDisableTiming);
        attr_set = true;
    }

    // prep: weight split + layernorm/input split (one launch)
    prep_kernel<<<TP + NROWS, 256>>>(W_qkv, W_sem_down, W_ctx_down, W_sem_up,
                                     W_ctx_up, W_proj, x, gamma, beta);
    cudaEventRecord(evA, 0);
    cudaStreamWaitEvent(s_side, evA, 0);

    // main stream: qkv GEMM  (4096 x 2304 x 768)
    bgemm_kernel<1,128><<<dim3(3*DD/128, NROWS/128, 1), 256, SMEM128>>>(
        p_xn0, p_xn1, p_wq0, p_wq1, b_qkv, p_qkv, nullptr, nullptr, 3*DD, DD,
        nullptr, nullptr, nullptr, nullptr, nullptr, nullptr, nullptr);

    // side stream: down (silu, split out) then up
    bgemm_kernel<2,64><<<dim3(RR/64, NROWS/128, 2), 256, SMEM64, s_side>>>(
        p_x0, p_x1, p_wsd0, p_wsd1, nullptr, nullptr, p_hs0, p_hs1, RR, DD,
        nullptr, nullptr, p_wcd0, p_wcd1, nullptr, p_hc0, p_hc1);
    bgemm_kernel<0,128><<<dim3(2*DD/128, NROWS/128, 2), 256, SMEM128, s_side>>>(
        p_hs0, p_hs1, p_wsu0, p_wsu1, nullptr, p_sem, nullptr, nullptr, 2*DD, RR,
        p_hc0, p_hc1, p_wcu0, p_wcu1, p_ctx, nullptr, nullptr);
    cudaEventRecord(evB, s_side);
    cudaStreamWaitEvent(0, evB, 0);

    // fused gate + chunk sums
    gatechunk_kernel<<<dim3(NC, BHN), 256>>>(temperature, gate_out);
    scan_kernel<<<dim3(BHN, 16), 256>>>();
    attn_kernel<<<dim3(NC, BHN), 256, ATTN_SMEM>>>();

    // y = attn @ W_proj + b_proj        (4096 x 768 x 768)
    bgemm_kernel<1,128><<<dim3(DD/128, NROWS/128, 1), 256, SMEM128>>>(
        p_at0, p_at1, p_wp0, p_wp1, b_proj, y_out, nullptr, nullptr, DD, DD,
        nullptr, nullptr, nullptr, nullptr, nullptr, nullptr, nullptr);
}